// round 2
// baseline (speedup 1.0000x reference)
#include <cuda_runtime.h>
#include <math.h>

#define B_  2
#define N_  1024
#define T_  8
#define D_  128
#define H_  4
#define E_  8192
#define EP_ 9216          // E + N self loops
#define M_  16384         // B*N*T rows

// ---------------- scratch (device globals; no allocation allowed) ----------
__device__ float g_xl[M_ * 512];
__device__ float g_xr[M_ * 512];
__device__ float g_logits[EP_ * B_ * T_ * H_];   // (e,b,t,h) -> later p
__device__ float g_mx[B_ * N_ * T_ * H_];
__device__ float g_ssum[B_ * N_ * T_ * H_];
__device__ float g_agg[M_ * D_];
__device__ float g_qkv[M_ * 384];
__device__ float g_attno[M_ * D_];
__device__ float g_oproj[M_ * D_];
__device__ float g_x1[M_ * D_];
__device__ float g_hid[M_ * 512];
__device__ float g_f2[M_ * D_];
__device__ float g_cat[M_ * 256];   // [:,0:128]=x_sp  [:,128:256]=x_tp
__device__ float g_gate[M_ * D_];

// ---------------- helpers ---------------------------------------------------
__device__ __forceinline__ float warp_sum(float v) {
#pragma unroll
    for (int o = 16; o; o >>= 1) v += __shfl_xor_sync(0xFFFFFFFFu, v, o);
    return v;
}

__device__ __forceinline__ void atomicMaxFloat(float* addr, float val) {
    int old = __float_as_int(*addr);
    while (__int_as_float(old) < val) {
        int assumed = old;
        old = atomicCAS((int*)addr, assumed, __float_as_int(val));
        if (old == assumed) break;
    }
}

// ---------------- init scratch (must run every replay) ---------------------
__global__ void k_init() {
    int i = blockIdx.x * blockDim.x + threadIdx.x;
    if (i < B_ * N_ * T_ * H_) { g_mx[i] = -INFINITY; g_ssum[i] = 0.f; }
    if (i < M_ * D_) g_agg[i] = 0.f;
}

// ---------------- generic fp32 SGEMM: C = A(MxK) * B(KxN) [+bias][+act] ----
// mode: 0 none, 1 bias, 2 bias+gelu(exact), 3 bias+sigmoid
__global__ void sgemm(const float* __restrict__ A, const float* __restrict__ Bm,
                      const float* __restrict__ bias, float* __restrict__ C,
                      int M, int N, int K, int mode) {
    __shared__ float As[16][64];
    __shared__ float Bs[16][64];
    int tid = threadIdx.x;                 // 256 threads
    int tx = tid & 15, ty = tid >> 4;      // 16x16 threads, 4x4 micro tile
    int rowBase = blockIdx.y * 64;
    int colBase = blockIdx.x * 64;

    float acc[4][4];
#pragma unroll
    for (int i = 0; i < 4; i++)
#pragma unroll
        for (int j = 0; j < 4; j++) acc[i][j] = 0.f;

    int ra = tid >> 2;               // 0..63
    int ca = (tid & 3) << 2;         // 0,4,8,12
    int rb = tid >> 4;               // 0..15
    int cb = (tid & 15) << 2;        // 0..60

    for (int kt = 0; kt < K; kt += 16) {
        float4 av = *(const float4*)&A[(size_t)(rowBase + ra) * K + kt + ca];
        As[ca + 0][ra] = av.x; As[ca + 1][ra] = av.y;
        As[ca + 2][ra] = av.z; As[ca + 3][ra] = av.w;
        *(float4*)&Bs[rb][cb] =
            *(const float4*)&Bm[(size_t)(kt + rb) * N + colBase + cb];
        __syncthreads();
#pragma unroll
        for (int k = 0; k < 16; k++) {
            float4 a = *(float4*)&As[k][ty << 2];
            float4 b = *(float4*)&Bs[k][tx << 2];
            float ar[4] = {a.x, a.y, a.z, a.w};
            float br[4] = {b.x, b.y, b.z, b.w};
#pragma unroll
            for (int i = 0; i < 4; i++)
#pragma unroll
                for (int j = 0; j < 4; j++) acc[i][j] += ar[i] * br[j];
        }
        __syncthreads();
    }

    int col = colBase + (tx << 2);
    float4 bv = make_float4(0.f, 0.f, 0.f, 0.f);
    if (mode > 0) bv = *(const float4*)&bias[col];
#pragma unroll
    for (int i = 0; i < 4; i++) {
        int row = rowBase + (ty << 2) + i;
        float v[4];
#pragma unroll
        for (int j = 0; j < 4; j++) v[j] = acc[i][j];
        v[0] += bv.x; v[1] += bv.y; v[2] += bv.z; v[3] += bv.w;
        if (mode == 2) {
#pragma unroll
            for (int j = 0; j < 4; j++)
                v[j] = 0.5f * v[j] * (1.f + erff(v[j] * 0.70710678118654752f));
        } else if (mode == 3) {
#pragma unroll
            for (int j = 0; j < 4; j++)
                v[j] = 1.f / (1.f + __expf(-v[j]));
        }
        float4 o = make_float4(v[0], v[1], v[2], v[3]);
        *(float4*)&C[(size_t)row * N + col] = o;
    }
}

// ---------------- GAT: logits + segment max --------------------------------
__global__ void k_logits(const int* __restrict__ edges,
                         const float* __restrict__ att) {
    int w = (blockIdx.x * blockDim.x + threadIdx.x) >> 5;
    int lane = threadIdx.x & 31;
    if (w >= EP_ * B_ * T_) return;
    int e = w / (B_ * T_);
    int bt = w % (B_ * T_);
    int b = bt >> 3, t = bt & 7;
    int s, dn;
    if (e < E_) { s = edges[e]; dn = edges[E_ + e]; } else { s = dn = e - E_; }

    const float4* xl4 = (const float4*)(g_xl + (((size_t)(b * N_ + s)  * T_ + t) * 512));
    const float4* xr4 = (const float4*)(g_xr + (((size_t)(b * N_ + dn) * T_ + t) * 512));
    const float4* at4 = (const float4*)att;

#pragma unroll
    for (int h = 0; h < H_; h++) {
        float4 a = xl4[h * 32 + lane];
        float4 c = xr4[h * 32 + lane];
        float4 wv = at4[h * 32 + lane];
        float v0 = a.x + c.x; v0 = v0 > 0.f ? v0 : 0.2f * v0;
        float v1 = a.y + c.y; v1 = v1 > 0.f ? v1 : 0.2f * v1;
        float v2 = a.z + c.z; v2 = v2 > 0.f ? v2 : 0.2f * v2;
        float v3 = a.w + c.w; v3 = v3 > 0.f ? v3 : 0.2f * v3;
        float sum = wv.x * v0 + wv.y * v1 + wv.z * v2 + wv.w * v3;
        sum = warp_sum(sum);
        if (lane == 0) {
            g_logits[((size_t)(e * B_ + b) * T_ + t) * H_ + h] = sum;
            atomicMaxFloat(&g_mx[((b * N_ + dn) * T_ + t) * H_ + h], sum);
        }
    }
}

// ---------------- GAT: p = exp(logit - mx), segment sum --------------------
__global__ void k_p(const int* __restrict__ edges) {
    int i = blockIdx.x * blockDim.x + threadIdx.x;
    if (i >= EP_ * B_ * T_ * H_) return;
    int h = i & 3;
    int r = i >> 2;
    int t = r & 7; r >>= 3;
    int b = r & 1;
    int e = r >> 1;
    int dn = (e < E_) ? edges[E_ + e] : e - E_;
    int mi = ((b * N_ + dn) * T_ + t) * H_ + h;
    float p = __expf(g_logits[i] - g_mx[mi]);
    g_logits[i] = p;
    atomicAdd(&g_ssum[mi], p);
}

// ---------------- GAT: aggregate messages (mean over heads fused) ----------
__global__ void k_agg(const int* __restrict__ edges) {
    int w = (blockIdx.x * blockDim.x + threadIdx.x) >> 5;
    int lane = threadIdx.x & 31;
    if (w >= EP_ * B_ * T_) return;
    int e = w / (B_ * T_);
    int bt = w % (B_ * T_);
    int b = bt >> 3, t = bt & 7;
    int s, dn;
    if (e < E_) { s = edges[e]; dn = edges[E_ + e]; } else { s = dn = e - E_; }

    const float4* xl4 = (const float4*)(g_xl + (((size_t)(b * N_ + s) * T_ + t) * 512));
    size_t lbase = ((size_t)(e * B_ + b) * T_ + t) * H_;
    int mbase = ((b * N_ + dn) * T_ + t) * H_;

    float4 acc = make_float4(0.f, 0.f, 0.f, 0.f);
#pragma unroll
    for (int h = 0; h < H_; h++) {
        float alpha = g_logits[lbase + h] / g_ssum[mbase + h];
        alpha *= 0.25f;   // mean over H heads
        float4 a = xl4[h * 32 + lane];
        acc.x += alpha * a.x; acc.y += alpha * a.y;
        acc.z += alpha * a.z; acc.w += alpha * a.w;
    }
    float* dp = g_agg + ((size_t)(b * N_ + dn) * T_ + t) * D_ + lane * 4;
    atomicAdd(dp + 0, acc.x);
    atomicAdd(dp + 1, acc.y);
    atomicAdd(dp + 2, acc.z);
    atomicAdd(dp + 3, acc.w);
}

// ---------------- LayerNorm helpers (one warp per row of 128) --------------
__device__ __forceinline__ void ln_store(float4 v, const float* g, const float* b,
                                         float* out, int lane) {
    float mean = warp_sum(v.x + v.y + v.z + v.w) * (1.f / 128.f);
    float4 c = make_float4(v.x - mean, v.y - mean, v.z - mean, v.w - mean);
    float var = warp_sum(c.x * c.x + c.y * c.y + c.z * c.z + c.w * c.w) * (1.f / 128.f);
    float rs = rsqrtf(var + 1e-5f);
    float4 gv = *(const float4*)&g[lane * 4];
    float4 bv = *(const float4*)&b[lane * 4];
    float4 o = make_float4(c.x * rs * gv.x + bv.x, c.y * rs * gv.y + bv.y,
                           c.z * rs * gv.z + bv.z, c.w * rs * gv.w + bv.w);
    *(float4*)&out[lane * 4] = o;
}

__global__ void k_lns(const float* __restrict__ gat_b,
                      const float* __restrict__ g, const float* __restrict__ b) {
    int row = (blockIdx.x * blockDim.x + threadIdx.x) >> 5;
    int lane = threadIdx.x & 31;
    if (row >= M_) return;
    float4 v = *(const float4*)&g_agg[(size_t)row * D_ + lane * 4];
    float4 gb = *(const float4*)&gat_b[lane * 4];
    v.x += gb.x; v.y += gb.y; v.z += gb.z; v.w += gb.w;
    ln_store(v, g, b, &g_cat[(size_t)row * 256], lane);
}

__global__ void k_lnt1(const float* __restrict__ x,
                       const float* __restrict__ g, const float* __restrict__ b) {
    int row = (blockIdx.x * blockDim.x + threadIdx.x) >> 5;
    int lane = threadIdx.x & 31;
    if (row >= M_) return;
    float4 v  = *(const float4*)&x[(size_t)row * D_ + lane * 4];
    float4 v2 = *(const float4*)&g_oproj[(size_t)row * D_ + lane * 4];
    v.x += v2.x; v.y += v2.y; v.z += v2.z; v.w += v2.w;
    ln_store(v, g, b, &g_x1[(size_t)row * D_], lane);
}

__global__ void k_lnt2(const float* __restrict__ g, const float* __restrict__ b) {
    int row = (blockIdx.x * blockDim.x + threadIdx.x) >> 5;
    int lane = threadIdx.x & 31;
    if (row >= M_) return;
    float4 v  = *(const float4*)&g_x1[(size_t)row * D_ + lane * 4];
    float4 v2 = *(const float4*)&g_f2[(size_t)row * D_ + lane * 4];
    v.x += v2.x; v.y += v2.y; v.z += v2.z; v.w += v2.w;
    ln_store(v, g, b, &g_cat[(size_t)row * 256 + 128], lane);
}

__global__ void k_final(const float* __restrict__ x,
                        const float* __restrict__ g, const float* __restrict__ b,
                        float* __restrict__ out) {
    int row = (blockIdx.x * blockDim.x + threadIdx.x) >> 5;
    int lane = threadIdx.x & 31;
    if (row >= M_) return;
    float4 xsp = *(const float4*)&g_cat[(size_t)row * 256 + lane * 4];
    float4 xtp = *(const float4*)&g_cat[(size_t)row * 256 + 128 + lane * 4];
    float4 gt  = *(const float4*)&g_gate[(size_t)row * D_ + lane * 4];
    float4 xv  = *(const float4*)&x[(size_t)row * D_ + lane * 4];
    float4 v = make_float4(gt.x * xsp.x + (1.f - gt.x) * xtp.x + xv.x,
                           gt.y * xsp.y + (1.f - gt.y) * xtp.y + xv.y,
                           gt.z * xsp.z + (1.f - gt.z) * xtp.z + xv.z,
                           gt.w * xsp.w + (1.f - gt.w) * xtp.w + xv.w);
    ln_store(v, g, b, &out[(size_t)row * D_], lane);
}

// ---------------- temporal attention: one warp per (bn, h) -----------------
__global__ void k_attn() {
    int w = blockIdx.x * 4 + (threadIdx.x >> 5);
    int lane = threadIdx.x & 31;
    if (w >= (B_ * N_) * H_) return;
    int bn = w >> 2;
    int h = w & 3;

    float q[8], k[8], v[8];
#pragma unroll
    for (int t = 0; t < 8; t++) {
        size_t base = ((size_t)bn * 8 + t) * 384 + h * 32 + lane;
        q[t] = g_qkv[base];
        k[t] = g_qkv[base + 128];
        v[t] = g_qkv[base + 256];
    }
    const float scale = 0.17677669529663687f;  // 1/sqrt(32)
#pragma unroll
    for (int t = 0; t < 8; t++) {
        float sc[8];
#pragma unroll
        for (int s = 0; s < 8; s++) sc[s] = warp_sum(q[t] * k[s]) * scale;
        float mx = sc[0];
#pragma unroll
        for (int s = 1; s < 8; s++) mx = fmaxf(mx, sc[s]);
        float den = 0.f;
#pragma unroll
        for (int s = 0; s < 8; s++) { sc[s] = __expf(sc[s] - mx); den += sc[s]; }
        float inv = 1.f / den;
        float o = 0.f;
#pragma unroll
        for (int s = 0; s < 8; s++) o += sc[s] * v[s];
        o *= inv;
        g_attno[((size_t)bn * 8 + t) * D_ + h * 32 + lane] = o;
    }
}

// ---------------- launch ----------------------------------------------------
extern "C" void kernel_launch(void* const* d_in, const int* in_sizes, int n_in,
                              void* d_out, int out_size) {
    const float* x      = (const float*)d_in[0];
    const int*   edges  = (const int*)  d_in[1];
    const float* gat_wl = (const float*)d_in[2];
    const float* gat_wr = (const float*)d_in[3];
    const float* gat_att= (const float*)d_in[4];
    const float* gat_b  = (const float*)d_in[5];
    const float* in_w   = (const float*)d_in[6];
    const float* in_b   = (const float*)d_in[7];
    const float* out_w  = (const float*)d_in[8];
    const float* out_b  = (const float*)d_in[9];
    const float* ffn_w1 = (const float*)d_in[10];
    const float* ffn_b1 = (const float*)d_in[11];
    const float* ffn_w2 = (const float*)d_in[12];
    const float* ffn_b2 = (const float*)d_in[13];
    const float* fus_w  = (const float*)d_in[14];
    const float* fus_b  = (const float*)d_in[15];
    const float* lns_g  = (const float*)d_in[16];
    const float* lns_b  = (const float*)d_in[17];
    const float* lnt1_g = (const float*)d_in[18];
    const float* lnt1_b = (const float*)d_in[19];
    const float* lnt2_g = (const float*)d_in[20];
    const float* lnt2_b = (const float*)d_in[21];
    const float* lnf_g  = (const float*)d_in[22];
    const float* lnf_b  = (const float*)d_in[23];
    float* out = (float*)d_out;

    float *p_xl, *p_xr, *p_qkv, *p_attno, *p_oproj, *p_x1, *p_hid, *p_f2, *p_cat, *p_gate;
    cudaGetSymbolAddress((void**)&p_xl,    g_xl);
    cudaGetSymbolAddress((void**)&p_xr,    g_xr);
    cudaGetSymbolAddress((void**)&p_qkv,   g_qkv);
    cudaGetSymbolAddress((void**)&p_attno, g_attno);
    cudaGetSymbolAddress((void**)&p_oproj, g_oproj);
    cudaGetSymbolAddress((void**)&p_x1,    g_x1);
    cudaGetSymbolAddress((void**)&p_hid,   g_hid);
    cudaGetSymbolAddress((void**)&p_f2,    g_f2);
    cudaGetSymbolAddress((void**)&p_cat,   g_cat);
    cudaGetSymbolAddress((void**)&p_gate,  g_gate);

    // 0. init scratch (mx/ssum/agg) — must happen on every replay
    k_init<<<(M_ * D_) / 256, 256>>>();

    // 1. spatial projections xl = x@Wl, xr = x@Wr : (16384,128)@(128,512)
    sgemm<<<dim3(512 / 64, M_ / 64), 256>>>(x, gat_wl, nullptr, p_xl, M_, 512, 128, 0);
    sgemm<<<dim3(512 / 64, M_ / 64), 256>>>(x, gat_wr, nullptr, p_xr, M_, 512, 128, 0);

    // 2. GAT edge softmax + aggregation
    k_logits<<<(EP_ * B_ * T_) / 8, 256>>>(edges, gat_att);
    k_p<<<(EP_ * B_ * T_ * H_) / 256, 256>>>(edges);
    k_agg<<<(EP_ * B_ * T_) / 8, 256>>>(edges);
    k_lns<<<M_ / 8, 256>>>(gat_b, lns_g, lns_b);   // -> g_cat[:, :128]

    // 3. temporal attention
    sgemm<<<dim3(384 / 64, M_ / 64), 256>>>(x, in_w, in_b, p_qkv, M_, 384, 128, 1);
    k_attn<<<(B_ * N_ * H_) / 4, 128>>>();
    sgemm<<<dim3(128 / 64, M_ / 64), 256>>>(p_attno, out_w, out_b, p_oproj, M_, 128, 128, 1);
    k_lnt1<<<M_ / 8, 256>>>(x, lnt1_g, lnt1_b);

    // 4. FFN
    sgemm<<<dim3(512 / 64, M_ / 64), 256>>>(p_x1, ffn_w1, ffn_b1, p_hid, M_, 512, 128, 2);
    sgemm<<<dim3(128 / 64, M_ / 64), 256>>>(p_hid, ffn_w2, ffn_b2, p_f2, M_, 128, 512, 1);
    k_lnt2<<<M_ / 8, 256>>>(lnt2_g, lnt2_b);       // -> g_cat[:, 128:]

    // 5. gated fusion + final LN
    sgemm<<<dim3(128 / 64, M_ / 64), 256>>>(p_cat, fus_w, fus_b, p_gate, M_, 128, 256, 3);
    k_final<<<M_ / 8, 256>>>(x, lnf_g, lnf_b, out);
}

// round 4
// speedup vs baseline: 1.3091x; 1.3091x over previous
#include <cuda_runtime.h>
#include <cuda_bf16.h>
#include <math.h>
#include <stdint.h>

#define B_  2
#define N_  1024
#define T_  8
#define D_  128
#define H_  4
#define E_  8192
#define M_  16384
#define MAXDEG 128

// ---------------- scratch (device globals) ----------------------------------
__device__ __align__(256) float g_xlr[(size_t)M_ * 1024];   // [xl(512)|xr(512)]
__device__ __align__(256) float g_qkv[(size_t)M_ * 384];
__device__ __align__(256) float g_attno[(size_t)M_ * 128];
__device__ __align__(256) float g_oproj[(size_t)M_ * 128];
__device__ __align__(256) float g_x1[(size_t)M_ * 128];
__device__ __align__(256) float g_hid[(size_t)M_ * 512];
__device__ __align__(256) float g_f2[(size_t)M_ * 128];
__device__ __align__(256) float g_cat[(size_t)M_ * 256];    // [x_sp | x_tp]
__device__ __align__(256) float g_gate[(size_t)M_ * 128];
// weight splits: row n = [hi(K) | lo(K)] bf16
__device__ __align__(256) __nv_bfloat16 g_Bxlr[1024 * 256];
__device__ __align__(256) __nv_bfloat16 g_Bqkv[384 * 256];
__device__ __align__(256) __nv_bfloat16 g_Bout[128 * 256];
__device__ __align__(256) __nv_bfloat16 g_Bffn1[512 * 256];
__device__ __align__(256) __nv_bfloat16 g_Bffn2[128 * 1024];
__device__ __align__(256) __nv_bfloat16 g_Bfus[128 * 512];
// CSR
__device__ int g_deg[N_];
__device__ int g_csr[N_ * MAXDEG];

// ---------------- helpers ------------------------------------------------------
__device__ __forceinline__ float warp_sum(float v) {
#pragma unroll
    for (int o = 16; o; o >>= 1) v += __shfl_xor_sync(0xFFFFFFFFu, v, o);
    return v;
}
__device__ __forceinline__ uint32_t smem_u32(const void* p) {
    uint32_t a;
    asm("{ .reg .u64 t; cvta.to.shared.u64 t, %1; cvt.u32.u64 %0, t; }"
        : "=r"(a) : "l"(p));
    return a;
}
#define CP8(dst, src) \
    asm volatile("cp.async.ca.shared.global [%0], [%1], 8;" :: "r"(dst), "l"(src))

__device__ __forceinline__ void mma16816(float c[4], uint32_t a0, uint32_t a1,
                                         uint32_t a2, uint32_t a3,
                                         uint32_t b0, uint32_t b1) {
    asm volatile(
        "mma.sync.aligned.m16n8k16.row.col.f32.bf16.bf16.f32 "
        "{%0,%1,%2,%3}, {%4,%5,%6,%7}, {%8,%9}, {%0,%1,%2,%3};"
        : "+f"(c[0]), "+f"(c[1]), "+f"(c[2]), "+f"(c[3])
        : "r"(a0), "r"(a1), "r"(a2), "r"(a3), "r"(b0), "r"(b1));
}
__device__ __forceinline__ uint32_t packbf(float x, float y) {
    __nv_bfloat162 h = __floats2bfloat162_rn(x, y);
    return *(uint32_t*)&h;
}

// ---------------- init + CSR ----------------------------------------------------
__global__ void k_init0() {
    int n = blockIdx.x * blockDim.x + threadIdx.x;
    if (n < N_) { g_deg[n] = 1; g_csr[n * MAXDEG] = n; }   // self loop
}
__global__ void k_scatter(const int* __restrict__ edges) {
    int e = blockIdx.x * blockDim.x + threadIdx.x;
    if (e >= E_) return;
    int s = edges[e], d = edges[E_ + e];
    int pos = atomicAdd(&g_deg[d], 1);
    if (pos < MAXDEG) g_csr[d * MAXDEG + pos] = s;
}

// ---------------- weight splitting ----------------------------------------------
__global__ void k_splitw(const float* wl, const float* wr, const float* inw,
                         const float* outw, const float* f1w, const float* f2w,
                         const float* fw) {
    int job = blockIdx.y;
    int idx = blockIdx.x * 256 + threadIdx.x;
    const float* W; __nv_bfloat16* Bo; int K, Nw, coff = 0;
    switch (job) {
        case 0: W = wl;   Bo = g_Bxlr;  K = 128; Nw = 512; break;
        case 1: W = wr;   Bo = g_Bxlr;  K = 128; Nw = 512; coff = 512; break;
        case 2: W = inw;  Bo = g_Bqkv;  K = 128; Nw = 384; break;
        case 3: W = outw; Bo = g_Bout;  K = 128; Nw = 128; break;
        case 4: W = f1w;  Bo = g_Bffn1; K = 128; Nw = 512; break;
        case 5: W = f2w;  Bo = g_Bffn2; K = 512; Nw = 128; break;
        default:W = fw;   Bo = g_Bfus;  K = 256; Nw = 128; break;
    }
    if (idx >= K * Nw) return;
    int k = idx / Nw, n = idx % Nw;
    float v = W[idx];
    __nv_bfloat16 hi = __float2bfloat16(v);
    float lo = v - __bfloat162float(hi);
    size_t o = (size_t)(coff + n) * (size_t)(2 * K) + k;
    Bo[o] = hi;
    Bo[o + K] = __float2bfloat16(lo);
}

// ---------------- bf16x3 mma.sync GEMM -------------------------------------------
// C[M_ x Ng] = A(fp32 MxK) @ W ; W split in B2 (Ng rows x [hi(K)|lo(K)])
// block tile 128x128, panels of 16, 8 warps of 64x32
#define KPAD 24
__shared__ struct {} _dummy;

__global__ void __launch_bounds__(256, 1) hgemm(
        const float* __restrict__ A, const __nv_bfloat16* __restrict__ B2,
        const float* __restrict__ bias, float* __restrict__ C,
        int Ng, int K, int mode) {
    __shared__ __nv_bfloat16 sA[2][2][128][KPAD];
    __shared__ __nv_bfloat16 sB[2][2][128][KPAD];
    int tid = threadIdx.x, wid = tid >> 5, lane = tid & 31;
    int wm = wid >> 2, wn = wid & 3;          // 2 x 4 warp grid
    int rowBase = blockIdx.y * 128, colBase = blockIdx.x * 128;
    int nk = K >> 4;

    float acc[4][4][4];
#pragma unroll
    for (int i = 0; i < 4; i++)
#pragma unroll
        for (int j = 0; j < 4; j++)
#pragma unroll
            for (int q = 0; q < 4; q++) acc[i][j][q] = 0.f;

    int ar = tid >> 1, ah = tid & 1;          // A: row, k-half
    const float4* Abase = (const float4*)(A + (size_t)(rowBase + ar) * K + ah * 8);
    const char* Bb = (const char*)(B2 + (size_t)(colBase + ar) * (2 * K) + ah * K);

    // ---- loaders ----
    auto ldB = [&](int kt, int buf) {
        uint32_t dst = smem_u32(&sB[buf][ah][ar][0]);
        const char* src = Bb + kt * 32;
        CP8(dst, src); CP8(dst + 8, src + 8);
        CP8(dst + 16, src + 16); CP8(dst + 24, src + 24);
        asm volatile("cp.async.commit_group;" ::: "memory");
    };
    auto ldA = [&](int kt, int buf) {
        float4 v0 = Abase[kt * 4];
        float4 v1 = Abase[kt * 4 + 1];
        float f[8] = {v0.x, v0.y, v0.z, v0.w, v1.x, v1.y, v1.z, v1.w};
        uint32_t hp[4], lp[4];
#pragma unroll
        for (int i = 0; i < 4; i++) {
            __nv_bfloat16 h0 = __float2bfloat16(f[2*i]);
            __nv_bfloat16 h1 = __float2bfloat16(f[2*i+1]);
            float l0 = f[2*i]   - __bfloat162float(h0);
            float l1 = f[2*i+1] - __bfloat162float(h1);
            hp[i] = ((uint32_t)__bfloat16_as_ushort(h1) << 16) | __bfloat16_as_ushort(h0);
            lp[i] = packbf(l0, l1);
        }
        uint2* dh = (uint2*)&sA[buf][0][ar][ah * 8];
        uint2* dl = (uint2*)&sA[buf][1][ar][ah * 8];
        dh[0] = make_uint2(hp[0], hp[1]); dh[1] = make_uint2(hp[2], hp[3]);
        dl[0] = make_uint2(lp[0], lp[1]); dl[1] = make_uint2(lp[2], lp[3]);
    };

    ldB(0, 0); ldA(0, 0);
    asm volatile("cp.async.wait_group 0;" ::: "memory");
    __syncthreads();

    int buf = 0;
    int fr = lane >> 2, fc = (lane & 3) * 2;  // fragment row/col within tile
    for (int kt = 0; kt < nk; kt++) {
        if (kt + 1 < nk) { ldB(kt + 1, buf ^ 1); ldA(kt + 1, buf ^ 1); }

        uint32_t ahr[4][4], alr[4][4], bhr[4][2], blr[4][2];
#pragma unroll
        for (int mi = 0; mi < 4; mi++) {
            int r = wm * 64 + mi * 16 + fr;
            ahr[mi][0] = *(const uint32_t*)&sA[buf][0][r][fc];
            ahr[mi][1] = *(const uint32_t*)&sA[buf][0][r + 8][fc];
            ahr[mi][2] = *(const uint32_t*)&sA[buf][0][r][fc + 8];
            ahr[mi][3] = *(const uint32_t*)&sA[buf][0][r + 8][fc + 8];
            alr[mi][0] = *(const uint32_t*)&sA[buf][1][r][fc];
            alr[mi][1] = *(const uint32_t*)&sA[buf][1][r + 8][fc];
            alr[mi][2] = *(const uint32_t*)&sA[buf][1][r][fc + 8];
            alr[mi][3] = *(const uint32_t*)&sA[buf][1][r + 8][fc + 8];
        }
#pragma unroll
        for (int ni = 0; ni < 4; ni++) {
            int n = wn * 32 + ni * 8 + fr;
            bhr[ni][0] = *(const uint32_t*)&sB[buf][0][n][fc];
            bhr[ni][1] = *(const uint32_t*)&sB[buf][0][n][fc + 8];
            blr[ni][0] = *(const uint32_t*)&sB[buf][1][n][fc];
            blr[ni][1] = *(const uint32_t*)&sB[buf][1][n][fc + 8];
        }
#pragma unroll
        for (int mi = 0; mi < 4; mi++)
#pragma unroll
            for (int ni = 0; ni < 4; ni++) {
                mma16816(acc[mi][ni], ahr[mi][0], ahr[mi][1], ahr[mi][2], ahr[mi][3],
                         bhr[ni][0], bhr[ni][1]);
                mma16816(acc[mi][ni], ahr[mi][0], ahr[mi][1], ahr[mi][2], ahr[mi][3],
                         blr[ni][0], blr[ni][1]);
                mma16816(acc[mi][ni], alr[mi][0], alr[mi][1], alr[mi][2], alr[mi][3],
                         bhr[ni][0], bhr[ni][1]);
            }
        if (kt + 1 < nk) {
            asm volatile("cp.async.wait_group 0;" ::: "memory");
            __syncthreads();
            buf ^= 1;
        }
    }

    // ---- epilogue ----
#pragma unroll
    for (int mi = 0; mi < 4; mi++) {
        int r0 = rowBase + wm * 64 + mi * 16 + fr;
#pragma unroll
        for (int ni = 0; ni < 4; ni++) {
            int col = colBase + wn * 32 + ni * 8 + fc;
            float b0 = 0.f, b1 = 0.f;
            if (mode > 0) { b0 = bias[col]; b1 = bias[col + 1]; }
            float v[4] = {acc[mi][ni][0] + b0, acc[mi][ni][1] + b1,
                          acc[mi][ni][2] + b0, acc[mi][ni][3] + b1};
            if (mode == 2) {
#pragma unroll
                for (int q = 0; q < 4; q++)
                    v[q] = 0.5f * v[q] * (1.f + erff(v[q] * 0.70710678118654752f));
            } else if (mode == 3) {
#pragma unroll
                for (int q = 0; q < 4; q++) v[q] = 1.f / (1.f + __expf(-v[q]));
            }
            *(float2*)&C[(size_t)r0 * Ng + col]       = make_float2(v[0], v[1]);
            *(float2*)&C[(size_t)(r0 + 8) * Ng + col] = make_float2(v[2], v[3]);
        }
    }
}

// ---------------- fused GAT (online softmax, dst-centric) ------------------------
__global__ void k_gat(const float* __restrict__ att, const float* __restrict__ gat_b,
                      const float* __restrict__ lg, const float* __restrict__ lb) {
    int w = (blockIdx.x * blockDim.x + threadIdx.x) >> 5;   // row = (b*N+n)*T+t
    int lane = threadIdx.x & 31;
    if (w >= M_) return;
    int bn = w >> 3;
    int n = bn & (N_ - 1);
    int b = bn >> 10;
    int t = w & 7;

    const float4* xr4 = (const float4*)(g_xlr + (size_t)w * 1024 + 512);
    float4 xr[4], av[4];
#pragma unroll
    for (int h = 0; h < 4; h++) {
        xr[h] = xr4[h * 32 + lane];
        av[h] = ((const float4*)att)[h * 32 + lane];
    }
    float4 acc[4];
#pragma unroll
    for (int h = 0; h < 4; h++) acc[h] = make_float4(0.f, 0.f, 0.f, 0.f);
    float m[4] = {-INFINITY, -INFINITY, -INFINITY, -INFINITY};
    float s[4] = {0.f, 0.f, 0.f, 0.f};

    int deg = g_deg[n];
    if (deg > MAXDEG) deg = MAXDEG;
    const int* clist = g_csr + n * MAXDEG;

    for (int i = 0; i < deg; i++) {
        int src = clist[i];
        const float4* xl4 = (const float4*)(g_xlr + ((size_t)((b * N_ + src) * T_ + t)) * 1024);
        float4 xl[4];
        float lgt[4];
#pragma unroll
        for (int h = 0; h < 4; h++) {
            float4 a = xl4[h * 32 + lane];
            xl[h] = a;
            float v0 = a.x + xr[h].x; v0 = v0 > 0.f ? v0 : 0.2f * v0;
            float v1 = a.y + xr[h].y; v1 = v1 > 0.f ? v1 : 0.2f * v1;
            float v2 = a.z + xr[h].z; v2 = v2 > 0.f ? v2 : 0.2f * v2;
            float v3 = a.w + xr[h].w; v3 = v3 > 0.f ? v3 : 0.2f * v3;
            lgt[h] = warp_sum(av[h].x * v0 + av[h].y * v1 + av[h].z * v2 + av[h].w * v3);
        }
#pragma unroll
        for (int h = 0; h < 4; h++) {
            float nm = fmaxf(m[h], lgt[h]);
            float e0 = __expf(m[h] - nm);     // 0 when m = -inf first time
            float e1 = __expf(lgt[h] - nm);
            s[h] = s[h] * e0 + e1;
            acc[h].x = acc[h].x * e0 + e1 * xl[h].x;
            acc[h].y = acc[h].y * e0 + e1 * xl[h].y;
            acc[h].z = acc[h].z * e0 + e1 * xl[h].z;
            acc[h].w = acc[h].w * e0 + e1 * xl[h].w;
            m[h] = nm;
        }
    }

    float4 o = make_float4(0.f, 0.f, 0.f, 0.f);
#pragma unroll
    for (int h = 0; h < 4; h++) {
        float r = 0.25f / s[h];
        o.x += acc[h].x * r; o.y += acc[h].y * r;
        o.z += acc[h].z * r; o.w += acc[h].w * r;
    }
    float4 gb = *(const float4*)&gat_b[lane * 4];
    o.x += gb.x; o.y += gb.y; o.z += gb.z; o.w += gb.w;

    // LayerNorm + store to g_cat[:, :128]
    float mean = warp_sum(o.x + o.y + o.z + o.w) * (1.f / 128.f);
    float4 c = make_float4(o.x - mean, o.y - mean, o.z - mean, o.w - mean);
    float var = warp_sum(c.x * c.x + c.y * c.y + c.z * c.z + c.w * c.w) * (1.f / 128.f);
    float rs = rsqrtf(var + 1e-5f);
    float4 gv = *(const float4*)&lg[lane * 4];
    float4 bv = *(const float4*)&lb[lane * 4];
    *(float4*)&g_cat[(size_t)w * 256 + lane * 4] = make_float4(
        c.x * rs * gv.x + bv.x, c.y * rs * gv.y + bv.y,
        c.z * rs * gv.z + bv.z, c.w * rs * gv.w + bv.w);
}

// ---------------- LayerNorm -------------------------------------------------------
__device__ __forceinline__ void ln_store(float4 v, const float* g, const float* b,
                                         float* out, int lane) {
    float mean = warp_sum(v.x + v.y + v.z + v.w) * (1.f / 128.f);
    float4 c = make_float4(v.x - mean, v.y - mean, v.z - mean, v.w - mean);
    float var = warp_sum(c.x * c.x + c.y * c.y + c.z * c.z + c.w * c.w) * (1.f / 128.f);
    float rs = rsqrtf(var + 1e-5f);
    float4 gv = *(const float4*)&g[lane * 4];
    float4 bv = *(const float4*)&b[lane * 4];
    *(float4*)&out[lane * 4] = make_float4(
        c.x * rs * gv.x + bv.x, c.y * rs * gv.y + bv.y,
        c.z * rs * gv.z + bv.z, c.w * rs * gv.w + bv.w);
}

__global__ void k_lnt1(const float* __restrict__ x,
                       const float* __restrict__ g, const float* __restrict__ b) {
    int row = (blockIdx.x * blockDim.x + threadIdx.x) >> 5;
    int lane = threadIdx.x & 31;
    if (row >= M_) return;
    float4 v  = *(const float4*)&x[(size_t)row * D_ + lane * 4];
    float4 v2 = *(const float4*)&g_oproj[(size_t)row * D_ + lane * 4];
    v.x += v2.x; v.y += v2.y; v.z += v2.z; v.w += v2.w;
    ln_store(v, g, b, &g_x1[(size_t)row * D_], lane);
}

__global__ void k_lnt2(const float* __restrict__ g, const float* __restrict__ b) {
    int row = (blockIdx.x * blockDim.x + threadIdx.x) >> 5;
    int lane = threadIdx.x & 31;
    if (row >= M_) return;
    float4 v  = *(const float4*)&g_x1[(size_t)row * D_ + lane * 4];
    float4 v2 = *(const float4*)&g_f2[(size_t)row * D_ + lane * 4];
    v.x += v2.x; v.y += v2.y; v.z += v2.z; v.w += v2.w;
    ln_store(v, g, b, &g_cat[(size_t)row * 256 + 128], lane);
}

__global__ void k_final(const float* __restrict__ x,
                        const float* __restrict__ g, const float* __restrict__ b,
                        float* __restrict__ out) {
    int row = (blockIdx.x * blockDim.x + threadIdx.x) >> 5;
    int lane = threadIdx.x & 31;
    if (row >= M_) return;
    float4 xsp = *(const float4*)&g_cat[(size_t)row * 256 + lane * 4];
    float4 xtp = *(const float4*)&g_cat[(size_t)row * 256 + 128 + lane * 4];
    float4 gt  = *(const float4*)&g_gate[(size_t)row * D_ + lane * 4];
    float4 xv  = *(const float4*)&x[(size_t)row * D_ + lane * 4];
    float4 v = make_float4(gt.x * xsp.x + (1.f - gt.x) * xtp.x + xv.x,
                           gt.y * xsp.y + (1.f - gt.y) * xtp.y + xv.y,
                           gt.z * xsp.z + (1.f - gt.z) * xtp.z + xv.z,
                           gt.w * xsp.w + (1.f - gt.w) * xtp.w + xv.w);
    ln_store(v, g, b, &out[(size_t)row * D_], lane);
}

// ---------------- temporal attention ----------------------------------------------
__global__ void k_attn() {
    int w = blockIdx.x * 4 + (threadIdx.x >> 5);
    int lane = threadIdx.x & 31;
    if (w >= (B_ * N_) * H_) return;
    int bn = w >> 2;
    int h = w & 3;
    float q[8], k[8], v[8];
#pragma unroll
    for (int t = 0; t < 8; t++) {
        size_t base = ((size_t)bn * 8 + t) * 384 + h * 32 + lane;
        q[t] = g_qkv[base];
        k[t] = g_qkv[base + 128];
        v[t] = g_qkv[base + 256];
    }
    const float scale = 0.17677669529663687f;
#pragma unroll
    for (int t = 0; t < 8; t++) {
        float sc[8];
#pragma unroll
        for (int s = 0; s < 8; s++) sc[s] = warp_sum(q[t] * k[s]) * scale;
        float mx = sc[0];
#pragma unroll
        for (int s = 1; s < 8; s++) mx = fmaxf(mx, sc[s]);
        float den = 0.f;
#pragma unroll
        for (int s = 0; s < 8; s++) { sc[s] = __expf(sc[s] - mx); den += sc[s]; }
        float inv = 1.f / den;
        float o = 0.f;
#pragma unroll
        for (int s = 0; s < 8; s++) o += sc[s] * v[s];
        g_attno[((size_t)bn * 8 + t) * D_ + h * 32 + lane] = o * inv;
    }
}

// ---------------- launch -------------------------------------------------------------
extern "C" void kernel_launch(void* const* d_in, const int* in_sizes, int n_in,
                              void* d_out, int out_size) {
    const float* x      = (const float*)d_in[0];
    const int*   edges  = (const int*)  d_in[1];
    const float* gat_att= (const float*)d_in[4];
    const float* gat_b  = (const float*)d_in[5];
    const float* in_b   = (const float*)d_in[7];
    const float* out_b  = (const float*)d_in[9];
    const float* ffn_b1 = (const float*)d_in[11];
    const float* ffn_b2 = (const float*)d_in[13];
    const float* fus_b  = (const float*)d_in[15];
    const float* lns_g  = (const float*)d_in[16];
    const float* lns_b  = (const float*)d_in[17];
    const float* lnt1_g = (const float*)d_in[18];
    const float* lnt1_b = (const float*)d_in[19];
    const float* lnt2_g = (const float*)d_in[20];
    const float* lnt2_b = (const float*)d_in[21];
    const float* lnf_g  = (const float*)d_in[22];
    const float* lnf_b  = (const float*)d_in[23];
    float* out = (float*)d_out;

    float *p_xlr, *p_qkv, *p_attno, *p_oproj, *p_x1, *p_hid, *p_f2, *p_cat, *p_gate;
    __nv_bfloat16 *p_Bxlr, *p_Bqkv, *p_Bout, *p_Bffn1, *p_Bffn2, *p_Bfus;
    cudaGetSymbolAddress((void**)&p_xlr,   g_xlr);
    cudaGetSymbolAddress((void**)&p_qkv,   g_qkv);
    cudaGetSymbolAddress((void**)&p_attno, g_attno);
    cudaGetSymbolAddress((void**)&p_oproj, g_oproj);
    cudaGetSymbolAddress((void**)&p_x1,    g_x1);
    cudaGetSymbolAddress((void**)&p_hid,   g_hid);
    cudaGetSymbolAddress((void**)&p_f2,    g_f2);
    cudaGetSymbolAddress((void**)&p_cat,   g_cat);
    cudaGetSymbolAddress((void**)&p_gate,  g_gate);
    cudaGetSymbolAddress((void**)&p_Bxlr,  g_Bxlr);
    cudaGetSymbolAddress((void**)&p_Bqkv,  g_Bqkv);
    cudaGetSymbolAddress((void**)&p_Bout,  g_Bout);
    cudaGetSymbolAddress((void**)&p_Bffn1, g_Bffn1);
    cudaGetSymbolAddress((void**)&p_Bffn2, g_Bffn2);
    cudaGetSymbolAddress((void**)&p_Bfus,  g_Bfus);

    // prep: CSR + weight splits
    k_init0<<<4, 256>>>();
    k_scatter<<<E_ / 256, 256>>>(edges);
    k_splitw<<<dim3(256, 7), 256>>>((const float*)d_in[2], (const float*)d_in[3],
                                    (const float*)d_in[6], (const float*)d_in[8],
                                    (const float*)d_in[10], (const float*)d_in[12],
                                    (const float*)d_in[14]);

    // spatial: xlr = x @ [Wl|Wr], then fused GAT (-> g_cat[:, :128])
    hgemm<<<dim3(8, 128), 256>>>(x, p_Bxlr, nullptr, p_xlr, 1024, 128, 0);
    k_gat<<<M_ / 8, 256>>>(gat_att, gat_b, lns_g, lns_b);

    // temporal
    hgemm<<<dim3(3, 128), 256>>>(x, p_Bqkv, in_b, p_qkv, 384, 128, 1);
    k_attn<<<(B_ * N_ * H_) / 4, 128>>>();
    hgemm<<<dim3(1, 128), 256>>>(p_attno, p_Bout, out_b, p_oproj, 128, 128, 1);
    k_lnt1<<<M_ / 8, 256>>>(x, lnt1_g, lnt1_b);

    // FFN
    hgemm<<<dim3(4, 128), 256>>>(p_x1, p_Bffn1, ffn_b1, p_hid, 512, 128, 2);
    hgemm<<<dim3(1, 128), 256>>>(p_hid, p_Bffn2, ffn_b2, p_f2, 128, 512, 1);
    k_lnt2<<<M_ / 8, 256>>>(lnt2_g, lnt2_b);

    // fusion
    hgemm<<<dim3(1, 128), 256>>>(p_cat, p_Bfus, fus_b, p_gate, 128, 256, 3);
    k_final<<<M_ / 8, 256>>>(x, lnf_g, lnf_b, out);
}

// round 5
// speedup vs baseline: 1.5832x; 1.2094x over previous
#include <cuda_runtime.h>
#include <cuda_bf16.h>
#include <math.h>
#include <stdint.h>

#define B_  2
#define N_  1024
#define T_  8
#define D_  128
#define H_  4
#define E_  8192
#define M_  16384
#define MAXDEG 128

// ---------------- scratch (device globals) ----------------------------------
__device__ __align__(256) float g_xlr[(size_t)M_ * 1024];   // [xl(512)|xr(512)]
__device__ __align__(256) float g_qkv[(size_t)M_ * 384];
__device__ __align__(256) float g_attno[(size_t)M_ * 128];
__device__ __align__(256) float g_oproj[(size_t)M_ * 128];
__device__ __align__(256) float g_x1[(size_t)M_ * 128];
__device__ __align__(256) float g_hid[(size_t)M_ * 512];
__device__ __align__(256) float g_f2[(size_t)M_ * 128];
__device__ __align__(256) float g_cat[(size_t)M_ * 256];    // [x_sp | x_tp]
__device__ __align__(256) float g_gate[(size_t)M_ * 128];
// weight splits: row n = [hi(K) | lo(K)] bf16
__device__ __align__(256) __nv_bfloat16 g_Bxq[1408 * 256];  // [Wl|Wr|Wqkv]
__device__ __align__(256) float g_bias_xq[1408];
__device__ __align__(256) __nv_bfloat16 g_Bout[128 * 256];
__device__ __align__(256) __nv_bfloat16 g_Bffn1[512 * 256];
__device__ __align__(256) __nv_bfloat16 g_Bffn2[128 * 1024];
__device__ __align__(256) __nv_bfloat16 g_Bfus[128 * 512];
// CSR
__device__ int g_deg[N_];
__device__ int g_csr[N_ * MAXDEG];

// ---------------- helpers ------------------------------------------------------
__device__ __forceinline__ float warp_sum(float v) {
#pragma unroll
    for (int o = 16; o; o >>= 1) v += __shfl_xor_sync(0xFFFFFFFFu, v, o);
    return v;
}
__device__ __forceinline__ uint32_t smem_u32(const void* p) {
    uint32_t a;
    asm("{ .reg .u64 t; cvta.to.shared.u64 t, %1; cvt.u32.u64 %0, t; }"
        : "=r"(a) : "l"(p));
    return a;
}
#define CP8(dst, src) \
    asm volatile("cp.async.ca.shared.global [%0], [%1], 8;" :: "r"(dst), "l"(src))

__device__ __forceinline__ void mma16816(float c[4], uint32_t a0, uint32_t a1,
                                         uint32_t a2, uint32_t a3,
                                         uint32_t b0, uint32_t b1) {
    asm volatile(
        "mma.sync.aligned.m16n8k16.row.col.f32.bf16.bf16.f32 "
        "{%0,%1,%2,%3}, {%4,%5,%6,%7}, {%8,%9}, {%0,%1,%2,%3};"
        : "+f"(c[0]), "+f"(c[1]), "+f"(c[2]), "+f"(c[3])
        : "r"(a0), "r"(a1), "r"(a2), "r"(a3), "r"(b0), "r"(b1));
}
__device__ __forceinline__ uint32_t packbf(float x, float y) {
    __nv_bfloat162 h = __floats2bfloat162_rn(x, y);
    return *(uint32_t*)&h;
}

// ---------------- init + CSR + bias_xq -------------------------------------------
__global__ void k_init0(const float* __restrict__ in_b) {
    int i = blockIdx.x * blockDim.x + threadIdx.x;
    if (i < N_) { g_deg[i] = 1; g_csr[i * MAXDEG] = i; }   // self loop
    if (i < 1408) g_bias_xq[i] = (i < 1024) ? 0.f : in_b[i - 1024];
}
__global__ void k_scatter(const int* __restrict__ edges) {
    int e = blockIdx.x * blockDim.x + threadIdx.x;
    if (e >= E_) return;
    int s = edges[e], d = edges[E_ + e];
    int pos = atomicAdd(&g_deg[d], 1);
    if (pos < MAXDEG) g_csr[d * MAXDEG + pos] = s;
}

// ---------------- weight splitting ------------------------------------------------
__global__ void k_splitw(const float* wl, const float* wr, const float* inw,
                         const float* outw, const float* f1w, const float* f2w,
                         const float* fw) {
    int job = blockIdx.y;
    int idx = blockIdx.x * 256 + threadIdx.x;
    const float* W; __nv_bfloat16* Bo; int K, Nw, coff = 0;
    switch (job) {
        case 0: W = wl;   Bo = g_Bxq;   K = 128; Nw = 512; break;
        case 1: W = wr;   Bo = g_Bxq;   K = 128; Nw = 512; coff = 512; break;
        case 2: W = inw;  Bo = g_Bxq;   K = 128; Nw = 384; coff = 1024; break;
        case 3: W = outw; Bo = g_Bout;  K = 128; Nw = 128; break;
        case 4: W = f1w;  Bo = g_Bffn1; K = 128; Nw = 512; break;
        case 5: W = f2w;  Bo = g_Bffn2; K = 512; Nw = 128; break;
        default:W = fw;   Bo = g_Bfus;  K = 256; Nw = 128; break;
    }
    if (idx >= K * Nw) return;
    int k = idx / Nw, n = idx % Nw;
    float v = W[idx];
    __nv_bfloat16 hi = __float2bfloat16(v);
    float lo = v - __bfloat162float(hi);
    size_t o = (size_t)(coff + n) * (size_t)(2 * K) + k;
    Bo[o] = hi;
    Bo[o + K] = __float2bfloat16(lo);
}

// ---------------- bf16x3 mma.sync GEMM ---------------------------------------------
// C = A(fp32 MxK) @ W ; W split in B2 (rows x [hi(K)|lo(K)])
// CTA tile 128x128, 512 threads, 4x4 warp grid, warp tile 32x32, K-panels of 16.
// Dual destination: col < N1 -> C1 (stride s1), else C2 (stride s2, col-N1).
#define KPAD 24

__global__ void __launch_bounds__(512, 1) hgemm(
        const float* __restrict__ A, const __nv_bfloat16* __restrict__ B2,
        const float* __restrict__ bias,
        float* __restrict__ C1, int N1, int s1,
        float* __restrict__ C2, int s2,
        int K, int mode) {
    __shared__ __nv_bfloat16 sA[2][2][128][KPAD];
    __shared__ __nv_bfloat16 sB[2][2][128][KPAD];
    int tid = threadIdx.x, wid = tid >> 5, lane = tid & 31;
    int wm = wid >> 2, wn = wid & 3;          // 4 x 4 warp grid
    int rowBase = blockIdx.y * 128, colBase = blockIdx.x * 128;
    int nk = K >> 4;

    float acc[2][4][4];
#pragma unroll
    for (int i = 0; i < 2; i++)
#pragma unroll
        for (int j = 0; j < 4; j++)
#pragma unroll
            for (int q = 0; q < 4; q++) acc[i][j][q] = 0.f;

    int arow = tid >> 2, aq = tid & 3;
    const float4* Abase = (const float4*)(A + (size_t)(rowBase + arow) * K);
    const __nv_bfloat16* Brow = B2 + (size_t)(colBase + arow) * (2 * K);

    auto ldB = [&](int kt, int buf) {
        uint32_t dh = smem_u32(&sB[buf][0][arow][aq * 4]);
        uint32_t dl = smem_u32(&sB[buf][1][arow][aq * 4]);
        const char* hs = (const char*)(Brow + kt * 16 + aq * 4);
        CP8(dh, hs);
        CP8(dl, hs + 2 * K);
        asm volatile("cp.async.commit_group;" ::: "memory");
    };
    auto ldA = [&](int kt, int buf) {
        float4 v = Abase[kt * 4 + aq];
        __nv_bfloat16 h0 = __float2bfloat16(v.x), h1 = __float2bfloat16(v.y);
        __nv_bfloat16 h2 = __float2bfloat16(v.z), h3 = __float2bfloat16(v.w);
        uint2 hp, lp;
        hp.x = ((uint32_t)__bfloat16_as_ushort(h1) << 16) | __bfloat16_as_ushort(h0);
        hp.y = ((uint32_t)__bfloat16_as_ushort(h3) << 16) | __bfloat16_as_ushort(h2);
        lp.x = packbf(v.x - __bfloat162float(h0), v.y - __bfloat162float(h1));
        lp.y = packbf(v.z - __bfloat162float(h2), v.w - __bfloat162float(h3));
        *(uint2*)&sA[buf][0][arow][aq * 4] = hp;
        *(uint2*)&sA[buf][1][arow][aq * 4] = lp;
    };

    ldB(0, 0); ldA(0, 0);
    asm volatile("cp.async.wait_group 0;" ::: "memory");
    __syncthreads();

    int buf = 0;
    int fr = lane >> 2, fc = (lane & 3) * 2;
    for (int kt = 0; kt < nk; kt++) {
        if (kt + 1 < nk) { ldB(kt + 1, buf ^ 1); ldA(kt + 1, buf ^ 1); }

        uint32_t ahr[2][4], alr[2][4], bhr[4][2], blr[4][2];
#pragma unroll
        for (int mi = 0; mi < 2; mi++) {
            int r = wm * 32 + mi * 16 + fr;
            ahr[mi][0] = *(const uint32_t*)&sA[buf][0][r][fc];
            ahr[mi][1] = *(const uint32_t*)&sA[buf][0][r + 8][fc];
            ahr[mi][2] = *(const uint32_t*)&sA[buf][0][r][fc + 8];
            ahr[mi][3] = *(const uint32_t*)&sA[buf][0][r + 8][fc + 8];
            alr[mi][0] = *(const uint32_t*)&sA[buf][1][r][fc];
            alr[mi][1] = *(const uint32_t*)&sA[buf][1][r + 8][fc];
            alr[mi][2] = *(const uint32_t*)&sA[buf][1][r][fc + 8];
            alr[mi][3] = *(const uint32_t*)&sA[buf][1][r + 8][fc + 8];
        }
#pragma unroll
        for (int ni = 0; ni < 4; ni++) {
            int n = wn * 32 + ni * 8 + fr;
            bhr[ni][0] = *(const uint32_t*)&sB[buf][0][n][fc];
            bhr[ni][1] = *(const uint32_t*)&sB[buf][0][n][fc + 8];
            blr[ni][0] = *(const uint32_t*)&sB[buf][1][n][fc];
            blr[ni][1] = *(const uint32_t*)&sB[buf][1][n][fc + 8];
        }
#pragma unroll
        for (int mi = 0; mi < 2; mi++)
#pragma unroll
            for (int ni = 0; ni < 4; ni++) {
                mma16816(acc[mi][ni], ahr[mi][0], ahr[mi][1], ahr[mi][2], ahr[mi][3],
                         bhr[ni][0], bhr[ni][1]);
                mma16816(acc[mi][ni], ahr[mi][0], ahr[mi][1], ahr[mi][2], ahr[mi][3],
                         blr[ni][0], blr[ni][1]);
                mma16816(acc[mi][ni], alr[mi][0], alr[mi][1], alr[mi][2], alr[mi][3],
                         bhr[ni][0], bhr[ni][1]);
            }
        if (kt + 1 < nk) {
            asm volatile("cp.async.wait_group 0;" ::: "memory");
            __syncthreads();
            buf ^= 1;
        }
    }

    // ---- epilogue ----
#pragma unroll
    for (int mi = 0; mi < 2; mi++) {
        int r0 = rowBase + wm * 32 + mi * 16 + fr;
#pragma unroll
        for (int ni = 0; ni < 4; ni++) {
            int col = colBase + wn * 32 + ni * 8 + fc;
            float b0 = 0.f, b1 = 0.f;
            if (mode > 0) { b0 = bias[col]; b1 = bias[col + 1]; }
            float v[4] = {acc[mi][ni][0] + b0, acc[mi][ni][1] + b1,
                          acc[mi][ni][2] + b0, acc[mi][ni][3] + b1};
            if (mode == 2) {
#pragma unroll
                for (int q = 0; q < 4; q++)
                    v[q] = 0.5f * v[q] * (1.f + erff(v[q] * 0.70710678118654752f));
            } else if (mode == 3) {
#pragma unroll
                for (int q = 0; q < 4; q++) v[q] = 1.f / (1.f + __expf(-v[q]));
            }
            if (col < N1) {
                *(float2*)&C1[(size_t)r0 * s1 + col]       = make_float2(v[0], v[1]);
                *(float2*)&C1[(size_t)(r0 + 8) * s1 + col] = make_float2(v[2], v[3]);
            } else {
                int c2 = col - N1;
                *(float2*)&C2[(size_t)r0 * s2 + c2]        = make_float2(v[0], v[1]);
                *(float2*)&C2[(size_t)(r0 + 8) * s2 + c2]  = make_float2(v[2], v[3]);
            }
        }
    }
}

// ---------------- fused GAT (online softmax, dst-centric) --------------------------
__global__ void k_gat(const float* __restrict__ att, const float* __restrict__ gat_b,
                      const float* __restrict__ lg, const float* __restrict__ lb) {
    int w = (blockIdx.x * blockDim.x + threadIdx.x) >> 5;   // row = (b*N+n)*T+t
    int lane = threadIdx.x & 31;
    if (w >= M_) return;
    int bn = w >> 3;
    int n = bn & (N_ - 1);
    int b = bn >> 10;
    int t = w & 7;

    const float4* xr4 = (const float4*)(g_xlr + (size_t)w * 1024 + 512);
    float4 xr[4], av[4];
#pragma unroll
    for (int h = 0; h < 4; h++) {
        xr[h] = xr4[h * 32 + lane];
        av[h] = ((const float4*)att)[h * 32 + lane];
    }
    float4 acc[4];
#pragma unroll
    for (int h = 0; h < 4; h++) acc[h] = make_float4(0.f, 0.f, 0.f, 0.f);
    float m[4] = {-INFINITY, -INFINITY, -INFINITY, -INFINITY};
    float s[4] = {0.f, 0.f, 0.f, 0.f};

    int deg = g_deg[n];
    if (deg > MAXDEG) deg = MAXDEG;
    const int* clist = g_csr + n * MAXDEG;

    for (int i = 0; i < deg; i++) {
        int src = clist[i];
        const float4* xl4 = (const float4*)(g_xlr + ((size_t)((b * N_ + src) * T_ + t)) * 1024);
        float4 xl[4];
        float lgt[4];
#pragma unroll
        for (int h = 0; h < 4; h++) {
            float4 a = xl4[h * 32 + lane];
            xl[h] = a;
            float v0 = a.x + xr[h].x; v0 = v0 > 0.f ? v0 : 0.2f * v0;
            float v1 = a.y + xr[h].y; v1 = v1 > 0.f ? v1 : 0.2f * v1;
            float v2 = a.z + xr[h].z; v2 = v2 > 0.f ? v2 : 0.2f * v2;
            float v3 = a.w + xr[h].w; v3 = v3 > 0.f ? v3 : 0.2f * v3;
            lgt[h] = warp_sum(av[h].x * v0 + av[h].y * v1 + av[h].z * v2 + av[h].w * v3);
        }
#pragma unroll
        for (int h = 0; h < 4; h++) {
            float nm = fmaxf(m[h], lgt[h]);
            float e0 = __expf(m[h] - nm);
            float e1 = __expf(lgt[h] - nm);
            s[h] = s[h] * e0 + e1;
            acc[h].x = acc[h].x * e0 + e1 * xl[h].x;
            acc[h].y = acc[h].y * e0 + e1 * xl[h].y;
            acc[h].z = acc[h].z * e0 + e1 * xl[h].z;
            acc[h].w = acc[h].w * e0 + e1 * xl[h].w;
            m[h] = nm;
        }
    }

    float4 o = make_float4(0.f, 0.f, 0.f, 0.f);
#pragma unroll
    for (int h = 0; h < 4; h++) {
        float r = 0.25f / s[h];
        o.x += acc[h].x * r; o.y += acc[h].y * r;
        o.z += acc[h].z * r; o.w += acc[h].w * r;
    }
    float4 gb = *(const float4*)&gat_b[lane * 4];
    o.x += gb.x; o.y += gb.y; o.z += gb.z; o.w += gb.w;

    float mean = warp_sum(o.x + o.y + o.z + o.w) * (1.f / 128.f);
    float4 c = make_float4(o.x - mean, o.y - mean, o.z - mean, o.w - mean);
    float var = warp_sum(c.x * c.x + c.y * c.y + c.z * c.z + c.w * c.w) * (1.f / 128.f);
    float rs = rsqrtf(var + 1e-5f);
    float4 gv = *(const float4*)&lg[lane * 4];
    float4 bv = *(const float4*)&lb[lane * 4];
    *(float4*)&g_cat[(size_t)w * 256 + lane * 4] = make_float4(
        c.x * rs * gv.x + bv.x, c.y * rs * gv.y + bv.y,
        c.z * rs * gv.z + bv.z, c.w * rs * gv.w + bv.w);
}

// ---------------- LayerNorm ---------------------------------------------------------
__device__ __forceinline__ void ln_store(float4 v, const float* g, const float* b,
                                         float* out, int lane) {
    float mean = warp_sum(v.x + v.y + v.z + v.w) * (1.f / 128.f);
    float4 c = make_float4(v.x - mean, v.y - mean, v.z - mean, v.w - mean);
    float var = warp_sum(c.x * c.x + c.y * c.y + c.z * c.z + c.w * c.w) * (1.f / 128.f);
    float rs = rsqrtf(var + 1e-5f);
    float4 gv = *(const float4*)&g[lane * 4];
    float4 bv = *(const float4*)&b[lane * 4];
    *(float4*)&out[lane * 4] = make_float4(
        c.x * rs * gv.x + bv.x, c.y * rs * gv.y + bv.y,
        c.z * rs * gv.z + bv.z, c.w * rs * gv.w + bv.w);
}

__global__ void k_lnt1(const float* __restrict__ x,
                       const float* __restrict__ g, const float* __restrict__ b) {
    int row = (blockIdx.x * blockDim.x + threadIdx.x) >> 5;
    int lane = threadIdx.x & 31;
    if (row >= M_) return;
    float4 v  = *(const float4*)&x[(size_t)row * D_ + lane * 4];
    float4 v2 = *(const float4*)&g_oproj[(size_t)row * D_ + lane * 4];
    v.x += v2.x; v.y += v2.y; v.z += v2.z; v.w += v2.w;
    ln_store(v, g, b, &g_x1[(size_t)row * D_], lane);
}

__global__ void k_lnt2(const float* __restrict__ g, const float* __restrict__ b) {
    int row = (blockIdx.x * blockDim.x + threadIdx.x) >> 5;
    int lane = threadIdx.x & 31;
    if (row >= M_) return;
    float4 v  = *(const float4*)&g_x1[(size_t)row * D_ + lane * 4];
    float4 v2 = *(const float4*)&g_f2[(size_t)row * D_ + lane * 4];
    v.x += v2.x; v.y += v2.y; v.z += v2.z; v.w += v2.w;
    ln_store(v, g, b, &g_cat[(size_t)row * 256 + 128], lane);
}

__global__ void k_final(const float* __restrict__ x,
                        const float* __restrict__ g, const float* __restrict__ b,
                        float* __restrict__ out) {
    int row = (blockIdx.x * blockDim.x + threadIdx.x) >> 5;
    int lane = threadIdx.x & 31;
    if (row >= M_) return;
    float4 xsp = *(const float4*)&g_cat[(size_t)row * 256 + lane * 4];
    float4 xtp = *(const float4*)&g_cat[(size_t)row * 256 + 128 + lane * 4];
    float4 gt  = *(const float4*)&g_gate[(size_t)row * D_ + lane * 4];
    float4 xv  = *(const float4*)&x[(size_t)row * D_ + lane * 4];
    float4 v = make_float4(gt.x * xsp.x + (1.f - gt.x) * xtp.x + xv.x,
                           gt.y * xsp.y + (1.f - gt.y) * xtp.y + xv.y,
                           gt.z * xsp.z + (1.f - gt.z) * xtp.z + xv.z,
                           gt.w * xsp.w + (1.f - gt.w) * xtp.w + xv.w);
    ln_store(v, g, b, &out[(size_t)row * D_], lane);
}

// ---------------- temporal attention ------------------------------------------------
__global__ void k_attn() {
    int w = blockIdx.x * 4 + (threadIdx.x >> 5);
    int lane = threadIdx.x & 31;
    if (w >= (B_ * N_) * H_) return;
    int bn = w >> 2;
    int h = w & 3;
    float q[8], k[8], v[8];
#pragma unroll
    for (int t = 0; t < 8; t++) {
        size_t base = ((size_t)bn * 8 + t) * 384 + h * 32 + lane;
        q[t] = g_qkv[base];
        k[t] = g_qkv[base + 128];
        v[t] = g_qkv[base + 256];
    }
    const float scale = 0.17677669529663687f;
#pragma unroll
    for (int t = 0; t < 8; t++) {
        float sc[8];
#pragma unroll
        for (int s = 0; s < 8; s++) sc[s] = warp_sum(q[t] * k[s]) * scale;
        float mx = sc[0];
#pragma unroll
        for (int s = 1; s < 8; s++) mx = fmaxf(mx, sc[s]);
        float den = 0.f;
#pragma unroll
        for (int s = 0; s < 8; s++) { sc[s] = __expf(sc[s] - mx); den += sc[s]; }
        float inv = 1.f / den;
        float o = 0.f;
#pragma unroll
        for (int s = 0; s < 8; s++) o += sc[s] * v[s];
        g_attno[((size_t)bn * 8 + t) * D_ + h * 32 + lane] = o * inv;
    }
}

// ---------------- launch ---------------------------------------------------------------
extern "C" void kernel_launch(void* const* d_in, const int* in_sizes, int n_in,
                              void* d_out, int out_size) {
    const float* x      = (const float*)d_in[0];
    const int*   edges  = (const int*)  d_in[1];
    const float* gat_att= (const float*)d_in[4];
    const float* gat_b  = (const float*)d_in[5];
    const float* in_b   = (const float*)d_in[7];
    const float* out_b  = (const float*)d_in[9];
    const float* ffn_b1 = (const float*)d_in[11];
    const float* ffn_b2 = (const float*)d_in[13];
    const float* fus_b  = (const float*)d_in[15];
    const float* lns_g  = (const float*)d_in[16];
    const float* lns_b  = (const float*)d_in[17];
    const float* lnt1_g = (const float*)d_in[18];
    const float* lnt1_b = (const float*)d_in[19];
    const float* lnt2_g = (const float*)d_in[20];
    const float* lnt2_b = (const float*)d_in[21];
    const float* lnf_g  = (const float*)d_in[22];
    const float* lnf_b  = (const float*)d_in[23];
    float* out = (float*)d_out;

    float *p_xlr, *p_qkv, *p_attno, *p_oproj, *p_x1, *p_hid, *p_f2, *p_cat, *p_gate, *p_bxq;
    __nv_bfloat16 *p_Bxq, *p_Bout, *p_Bffn1, *p_Bffn2, *p_Bfus;
    cudaGetSymbolAddress((void**)&p_xlr,   g_xlr);
    cudaGetSymbolAddress((void**)&p_qkv,   g_qkv);
    cudaGetSymbolAddress((void**)&p_attno, g_attno);
    cudaGetSymbolAddress((void**)&p_oproj, g_oproj);
    cudaGetSymbolAddress((void**)&p_x1,    g_x1);
    cudaGetSymbolAddress((void**)&p_hid,   g_hid);
    cudaGetSymbolAddress((void**)&p_f2,    g_f2);
    cudaGetSymbolAddress((void**)&p_cat,   g_cat);
    cudaGetSymbolAddress((void**)&p_gate,  g_gate);
    cudaGetSymbolAddress((void**)&p_bxq,   g_bias_xq);
    cudaGetSymbolAddress((void**)&p_Bxq,   g_Bxq);
    cudaGetSymbolAddress((void**)&p_Bout,  g_Bout);
    cudaGetSymbolAddress((void**)&p_Bffn1, g_Bffn1);
    cudaGetSymbolAddress((void**)&p_Bffn2, g_Bffn2);
    cudaGetSymbolAddress((void**)&p_Bfus,  g_Bfus);

    // prep: CSR + bias + weight splits
    k_init0<<<6, 256>>>(in_b);
    k_scatter<<<E_ / 256, 256>>>(edges);
    k_splitw<<<dim3(256, 7), 256>>>((const float*)d_in[2], (const float*)d_in[3],
                                    (const float*)d_in[6], (const float*)d_in[8],
                                    (const float*)d_in[10], (const float*)d_in[12],
                                    (const float*)d_in[14]);

    // merged spatial+qkv: [xlr | qkv] = x @ [Wl|Wr|Wqkv]
    hgemm<<<dim3(11, 128), 512>>>(x, p_Bxq, p_bxq,
                                  p_xlr, 1024, 1024, p_qkv, 384, 128, 1);
    k_gat<<<M_ / 8, 256>>>(gat_att, gat_b, lns_g, lns_b);

    // temporal
    k_attn<<<(B_ * N_ * H_) / 4, 128>>>();
    hgemm<<<dim3(1, 128), 512>>>(p_attno, p_Bout, out_b,
                                 p_oproj, 128, 128, p_oproj, 128, 128, 1);
    k_lnt1<<<M_ / 8, 256>>>(x, lnt1_g, lnt1_b);

    // FFN
    hgemm<<<dim3(4, 128), 512>>>(p_x1, p_Bffn1, ffn_b1,
                                 p_hid, 512, 512, p_hid, 512, 128, 2);
    hgemm<<<dim3(1, 128), 512>>>(p_hid, p_Bffn2, ffn_b2,
                                 p_f2, 128, 128, p_f2, 128, 512, 1);
    k_lnt2<<<M_ / 8, 256>>>(lnt2_g, lnt2_b);

    // fusion
    hgemm<<<dim3(1, 128), 512>>>(p_cat, p_Bfus, fus_b,
                                 p_gate, 128, 128, p_gate, 128, 256, 3);
    k_final<<<M_ / 8, 256>>>(x, lnf_g, lnf_b, out);
}

// round 6
// speedup vs baseline: 1.6109x; 1.0175x over previous
#include <cuda_runtime.h>
#include <cuda_bf16.h>
#include <math.h>
#include <stdint.h>

#define B_  2
#define N_  1024
#define T_  8
#define D_  128
#define H_  4
#define E_  8192
#define M_  16384
#define MAXDEG 128

// ---------------- scratch (device globals) ----------------------------------
__device__ __align__(256) float g_xlr[(size_t)M_ * 1024];   // [xl(512)|xr(512)]
__device__ __align__(256) float g_qkv[(size_t)M_ * 384];
__device__ __align__(256) float g_attno[(size_t)M_ * 128];
__device__ __align__(256) float g_oproj[(size_t)M_ * 128];
__device__ __align__(256) float g_x1[(size_t)M_ * 128];
__device__ __align__(256) float g_hid[(size_t)M_ * 512];
__device__ __align__(256) float g_f2[(size_t)M_ * 128];
__device__ __align__(256) float g_cat[(size_t)M_ * 256];    // [x_sp | x_tp]
__device__ __align__(256) float g_gate[(size_t)M_ * 128];
// weight splits: row n = [hi(K) | lo(K)] bf16
__device__ __align__(256) __nv_bfloat16 g_Bxq[1408 * 256];  // [Wl|Wr|Wqkv]
__device__ __align__(256) float g_bias_xq[1408];
__device__ __align__(256) __nv_bfloat16 g_Bout[128 * 256];
__device__ __align__(256) __nv_bfloat16 g_Bffn1[512 * 256];
__device__ __align__(256) __nv_bfloat16 g_Bffn2[128 * 1024];
__device__ __align__(256) __nv_bfloat16 g_Bfus[128 * 512];
// CSR
__device__ int g_deg[N_];
__device__ int g_csr[N_ * MAXDEG];

// ---------------- helpers ------------------------------------------------------
__device__ __forceinline__ float warp_sum(float v) {
#pragma unroll
    for (int o = 16; o; o >>= 1) v += __shfl_xor_sync(0xFFFFFFFFu, v, o);
    return v;
}
__device__ __forceinline__ uint32_t smem_u32(const void* p) {
    uint32_t a;
    asm("{ .reg .u64 t; cvta.to.shared.u64 t, %1; cvt.u32.u64 %0, t; }"
        : "=r"(a) : "l"(p));
    return a;
}
#define CP8(dst, src) \
    asm volatile("cp.async.ca.shared.global [%0], [%1], 8;" :: "r"(dst), "l"(src))
#define LDSM4(r0, r1, r2, r3, addr) \
    asm volatile("ldmatrix.sync.aligned.m8n8.x4.shared.b16 {%0,%1,%2,%3}, [%4];" \
        : "=r"(r0), "=r"(r1), "=r"(r2), "=r"(r3) : "r"(addr))
#define LDSM2(r0, r1, addr) \
    asm volatile("ldmatrix.sync.aligned.m8n8.x2.shared.b16 {%0,%1}, [%2];" \
        : "=r"(r0), "=r"(r1) : "r"(addr))

__device__ __forceinline__ void mma16816(float c[4], uint32_t a0, uint32_t a1,
                                         uint32_t a2, uint32_t a3,
                                         uint32_t b0, uint32_t b1) {
    asm volatile(
        "mma.sync.aligned.m16n8k16.row.col.f32.bf16.bf16.f32 "
        "{%0,%1,%2,%3}, {%4,%5,%6,%7}, {%8,%9}, {%0,%1,%2,%3};"
        : "+f"(c[0]), "+f"(c[1]), "+f"(c[2]), "+f"(c[3])
        : "r"(a0), "r"(a1), "r"(a2), "r"(a3), "r"(b0), "r"(b1));
}
__device__ __forceinline__ uint32_t packbf(float x, float y) {
    __nv_bfloat162 h = __floats2bfloat162_rn(x, y);
    return *(uint32_t*)&h;
}

// ---------------- init + CSR + bias_xq -------------------------------------------
__global__ void k_init0(const float* __restrict__ in_b) {
    int i = blockIdx.x * blockDim.x + threadIdx.x;
    if (i < N_) { g_deg[i] = 1; g_csr[i * MAXDEG] = i; }   // self loop
    if (i < 1408) g_bias_xq[i] = (i < 1024) ? 0.f : in_b[i - 1024];
}
__global__ void k_scatter(const int* __restrict__ edges) {
    int e = blockIdx.x * blockDim.x + threadIdx.x;
    if (e >= E_) return;
    int s = edges[e], d = edges[E_ + e];
    int pos = atomicAdd(&g_deg[d], 1);
    if (pos < MAXDEG) g_csr[d * MAXDEG + pos] = s;
}

// ---------------- weight splitting ------------------------------------------------
__global__ void k_splitw(const float* wl, const float* wr, const float* inw,
                         const float* outw, const float* f1w, const float* f2w,
                         const float* fw) {
    int job = blockIdx.y;
    int idx = blockIdx.x * 256 + threadIdx.x;
    const float* W; __nv_bfloat16* Bo; int K, Nw, coff = 0;
    switch (job) {
        case 0: W = wl;   Bo = g_Bxq;   K = 128; Nw = 512; break;
        case 1: W = wr;   Bo = g_Bxq;   K = 128; Nw = 512; coff = 512; break;
        case 2: W = inw;  Bo = g_Bxq;   K = 128; Nw = 384; coff = 1024; break;
        case 3: W = outw; Bo = g_Bout;  K = 128; Nw = 128; break;
        case 4: W = f1w;  Bo = g_Bffn1; K = 128; Nw = 512; break;
        case 5: W = f2w;  Bo = g_Bffn2; K = 512; Nw = 128; break;
        default:W = fw;   Bo = g_Bfus;  K = 256; Nw = 128; break;
    }
    if (idx >= K * Nw) return;
    int k = idx / Nw, n = idx % Nw;
    float v = W[idx];
    __nv_bfloat16 hi = __float2bfloat16(v);
    float lo = v - __bfloat162float(hi);
    size_t o = (size_t)(coff + n) * (size_t)(2 * K) + k;
    Bo[o] = hi;
    Bo[o + K] = __float2bfloat16(lo);
}

// ---------------- bf16x3 mma.sync GEMM ---------------------------------------------
// C = A(fp32 MxK) @ W ; W split in B2 (rows x [hi(K)|lo(K)])
// CTA tile 128x128, 512 threads, 4x4 warp grid, warp tile 32x32, K-panels of 16.
// 3-stage cp.async pipeline, ldmatrix fragment loads.
// Dual destination: col < N1 -> C1 (stride s1), else C2 (stride s2, col-N1).
#define KPAD 24
#define PLANE (128 * KPAD)
#define SMEMSZ (12 * PLANE * 2)

__global__ void __launch_bounds__(512, 1) hgemm(
        const float* __restrict__ A, const __nv_bfloat16* __restrict__ B2,
        const float* __restrict__ bias,
        float* __restrict__ C1, int N1, int s1,
        float* __restrict__ C2, int s2,
        int K, int mode) {
    extern __shared__ __nv_bfloat16 sm[];
    __nv_bfloat16* sAp = sm;               // [3 bufs][2 planes][128][KPAD]
    __nv_bfloat16* sBp = sm + 6 * PLANE;
    int tid = threadIdx.x, wid = tid >> 5, lane = tid & 31;
    int wm = wid >> 2, wn = wid & 3;
    int rowBase = blockIdx.y * 128, colBase = blockIdx.x * 128;
    int nk = K >> 4;

    float acc[2][4][4];
#pragma unroll
    for (int i = 0; i < 2; i++)
#pragma unroll
        for (int j = 0; j < 4; j++)
#pragma unroll
            for (int q = 0; q < 4; q++) acc[i][j][q] = 0.f;

    int arow = tid >> 2, aq = tid & 3;
    const float4* Abase = (const float4*)(A + (size_t)(rowBase + arow) * K);
    const __nv_bfloat16* Brow = B2 + (size_t)(colBase + arow) * (2 * K);

    auto ld = [&](int kt, int buf) {
        uint32_t dh = smem_u32(sBp + ((buf * 2 + 0) * 128 + arow) * KPAD + aq * 4);
        uint32_t dl = smem_u32(sBp + ((buf * 2 + 1) * 128 + arow) * KPAD + aq * 4);
        const char* hs = (const char*)(Brow + kt * 16 + aq * 4);
        CP8(dh, hs);
        CP8(dl, hs + 2 * K);                 // lo plane at +K elements
        float4 v = Abase[kt * 4 + aq];
        __nv_bfloat16 h0 = __float2bfloat16(v.x), h1 = __float2bfloat16(v.y);
        __nv_bfloat16 h2 = __float2bfloat16(v.z), h3 = __float2bfloat16(v.w);
        uint2 hp, lp;
        hp.x = ((uint32_t)__bfloat16_as_ushort(h1) << 16) | __bfloat16_as_ushort(h0);
        hp.y = ((uint32_t)__bfloat16_as_ushort(h3) << 16) | __bfloat16_as_ushort(h2);
        lp.x = packbf(v.x - __bfloat162float(h0), v.y - __bfloat162float(h1));
        lp.y = packbf(v.z - __bfloat162float(h2), v.w - __bfloat162float(h3));
        *(uint2*)(sAp + ((buf * 2 + 0) * 128 + arow) * KPAD + aq * 4) = hp;
        *(uint2*)(sAp + ((buf * 2 + 1) * 128 + arow) * KPAD + aq * 4) = lp;
        asm volatile("cp.async.commit_group;" ::: "memory");
    };

    ld(0, 0);
    if (nk > 1) ld(1, 1);

    int arf = (lane & 7) + ((lane >> 3) & 1) * 8;   // A frag row within 32
    int acol = ((lane >> 4) & 1) * 8;               // A frag k-half
    int brf = lane & 7;                             // B frag row within 8
    int bcol = ((lane >> 3) & 1) * 8;               // B frag k-half

    for (int kt = 0; kt < nk; kt++) {
        int buf = kt % 3;
        if (kt + 1 < nk) asm volatile("cp.async.wait_group 1;" ::: "memory");
        else             asm volatile("cp.async.wait_group 0;" ::: "memory");
        __syncthreads();
        if (kt + 2 < nk) ld(kt + 2, (kt + 2) % 3);

        uint32_t ah[2][4], al[2][4], bh[4][2], bl[4][2];
#pragma unroll
        for (int mi = 0; mi < 2; mi++) {
            uint32_t ad = smem_u32(sAp + ((buf * 2 + 0) * 128 + wm * 32 + mi * 16 + arf) * KPAD + acol);
            LDSM4(ah[mi][0], ah[mi][1], ah[mi][2], ah[mi][3], ad);
        }
#pragma unroll
        for (int ni = 0; ni < 4; ni++) {
            uint32_t bd = smem_u32(sBp + ((buf * 2 + 0) * 128 + wn * 32 + ni * 8 + brf) * KPAD + bcol);
            LDSM2(bh[ni][0], bh[ni][1], bd);
        }
#pragma unroll
        for (int mi = 0; mi < 2; mi++)
#pragma unroll
            for (int ni = 0; ni < 4; ni++)
                mma16816(acc[mi][ni], ah[mi][0], ah[mi][1], ah[mi][2], ah[mi][3],
                         bh[ni][0], bh[ni][1]);
#pragma unroll
        for (int mi = 0; mi < 2; mi++) {
            uint32_t ad = smem_u32(sAp + ((buf * 2 + 1) * 128 + wm * 32 + mi * 16 + arf) * KPAD + acol);
            LDSM4(al[mi][0], al[mi][1], al[mi][2], al[mi][3], ad);
        }
#pragma unroll
        for (int ni = 0; ni < 4; ni++) {
            uint32_t bd = smem_u32(sBp + ((buf * 2 + 1) * 128 + wn * 32 + ni * 8 + brf) * KPAD + bcol);
            LDSM2(bl[ni][0], bl[ni][1], bd);
        }
#pragma unroll
        for (int mi = 0; mi < 2; mi++)
#pragma unroll
            for (int ni = 0; ni < 4; ni++) {
                mma16816(acc[mi][ni], ah[mi][0], ah[mi][1], ah[mi][2], ah[mi][3],
                         bl[ni][0], bl[ni][1]);
                mma16816(acc[mi][ni], al[mi][0], al[mi][1], al[mi][2], al[mi][3],
                         bh[ni][0], bh[ni][1]);
            }
    }

    // ---- epilogue ----
    int fr = lane >> 2, fc = (lane & 3) * 2;
#pragma unroll
    for (int mi = 0; mi < 2; mi++) {
        int r0 = rowBase + wm * 32 + mi * 16 + fr;
#pragma unroll
        for (int ni = 0; ni < 4; ni++) {
            int col = colBase + wn * 32 + ni * 8 + fc;
            float b0 = 0.f, b1 = 0.f;
            if (mode > 0) { b0 = bias[col]; b1 = bias[col + 1]; }
            float v[4] = {acc[mi][ni][0] + b0, acc[mi][ni][1] + b1,
                          acc[mi][ni][2] + b0, acc[mi][ni][3] + b1};
            if (mode == 2) {
#pragma unroll
                for (int q = 0; q < 4; q++)
                    v[q] = 0.5f * v[q] * (1.f + erff(v[q] * 0.70710678118654752f));
            } else if (mode == 3) {
#pragma unroll
                for (int q = 0; q < 4; q++) v[q] = 1.f / (1.f + __expf(-v[q]));
            }
            if (col < N1) {
                *(float2*)&C1[(size_t)r0 * s1 + col]       = make_float2(v[0], v[1]);
                *(float2*)&C1[(size_t)(r0 + 8) * s1 + col] = make_float2(v[2], v[3]);
            } else {
                int c2 = col - N1;
                *(float2*)&C2[(size_t)r0 * s2 + c2]        = make_float2(v[0], v[1]);
                *(float2*)&C2[(size_t)(r0 + 8) * s2 + c2]  = make_float2(v[2], v[3]);
            }
        }
    }
}

// ---------------- fused GAT (online softmax, dst-centric) --------------------------
__global__ void k_gat(const float* __restrict__ att, const float* __restrict__ gat_b,
                      const float* __restrict__ lg, const float* __restrict__ lb) {
    int w = (blockIdx.x * blockDim.x + threadIdx.x) >> 5;   // row = (b*N+n)*T+t
    int lane = threadIdx.x & 31;
    if (w >= M_) return;
    int bn = w >> 3;
    int n = bn & (N_ - 1);
    int b = bn >> 10;
    int t = w & 7;

    const float4* xr4 = (const float4*)(g_xlr + (size_t)w * 1024 + 512);
    float4 xr[4], av[4];
#pragma unroll
    for (int h = 0; h < 4; h++) {
        xr[h] = xr4[h * 32 + lane];
        av[h] = ((const float4*)att)[h * 32 + lane];
    }
    float4 acc[4];
#pragma unroll
    for (int h = 0; h < 4; h++) acc[h] = make_float4(0.f, 0.f, 0.f, 0.f);
    float m[4] = {-INFINITY, -INFINITY, -INFINITY, -INFINITY};
    float s[4] = {0.f, 0.f, 0.f, 0.f};

    int deg = g_deg[n];
    if (deg > MAXDEG) deg = MAXDEG;
    const int* clist = g_csr + n * MAXDEG;

    for (int i = 0; i < deg; i++) {
        int src = clist[i];
        const float4* xl4 = (const float4*)(g_xlr + ((size_t)((b * N_ + src) * T_ + t)) * 1024);
        float4 xl[4];
        float lgt[4];
#pragma unroll
        for (int h = 0; h < 4; h++) {
            float4 a = xl4[h * 32 + lane];
            xl[h] = a;
            float v0 = a.x + xr[h].x; v0 = v0 > 0.f ? v0 : 0.2f * v0;
            float v1 = a.y + xr[h].y; v1 = v1 > 0.f ? v1 : 0.2f * v1;
            float v2 = a.z + xr[h].z; v2 = v2 > 0.f ? v2 : 0.2f * v2;
            float v3 = a.w + xr[h].w; v3 = v3 > 0.f ? v3 : 0.2f * v3;
            lgt[h] = warp_sum(av[h].x * v0 + av[h].y * v1 + av[h].z * v2 + av[h].w * v3);
        }
#pragma unroll
        for (int h = 0; h < 4; h++) {
            float nm = fmaxf(m[h], lgt[h]);
            float e0 = __expf(m[h] - nm);
            float e1 = __expf(lgt[h] - nm);
            s[h] = s[h] * e0 + e1;
            acc[h].x = acc[h].x * e0 + e1 * xl[h].x;
            acc[h].y = acc[h].y * e0 + e1 * xl[h].y;
            acc[h].z = acc[h].z * e0 + e1 * xl[h].z;
            acc[h].w = acc[h].w * e0 + e1 * xl[h].w;
            m[h] = nm;
        }
    }

    float4 o = make_float4(0.f, 0.f, 0.f, 0.f);
#pragma unroll
    for (int h = 0; h < 4; h++) {
        float r = 0.25f / s[h];
        o.x += acc[h].x * r; o.y += acc[h].y * r;
        o.z += acc[h].z * r; o.w += acc[h].w * r;
    }
    float4 gb = *(const float4*)&gat_b[lane * 4];
    o.x += gb.x; o.y += gb.y; o.z += gb.z; o.w += gb.w;

    float mean = warp_sum(o.x + o.y + o.z + o.w) * (1.f / 128.f);
    float4 c = make_float4(o.x - mean, o.y - mean, o.z - mean, o.w - mean);
    float var = warp_sum(c.x * c.x + c.y * c.y + c.z * c.z + c.w * c.w) * (1.f / 128.f);
    float rs = rsqrtf(var + 1e-5f);
    float4 gv = *(const float4*)&lg[lane * 4];
    float4 bv = *(const float4*)&lb[lane * 4];
    *(float4*)&g_cat[(size_t)w * 256 + lane * 4] = make_float4(
        c.x * rs * gv.x + bv.x, c.y * rs * gv.y + bv.y,
        c.z * rs * gv.z + bv.z, c.w * rs * gv.w + bv.w);
}

// ---------------- LayerNorm ---------------------------------------------------------
__device__ __forceinline__ void ln_store(float4 v, const float* g, const float* b,
                                         float* out, int lane) {
    float mean = warp_sum(v.x + v.y + v.z + v.w) * (1.f / 128.f);
    float4 c = make_float4(v.x - mean, v.y - mean, v.z - mean, v.w - mean);
    float var = warp_sum(c.x * c.x + c.y * c.y + c.z * c.z + c.w * c.w) * (1.f / 128.f);
    float rs = rsqrtf(var + 1e-5f);
    float4 gv = *(const float4*)&g[lane * 4];
    float4 bv = *(const float4*)&b[lane * 4];
    *(float4*)&out[lane * 4] = make_float4(
        c.x * rs * gv.x + bv.x, c.y * rs * gv.y + bv.y,
        c.z * rs * gv.z + bv.z, c.w * rs * gv.w + bv.w);
}

__global__ void k_lnt1(const float* __restrict__ x,
                       const float* __restrict__ g, const float* __restrict__ b) {
    int row = (blockIdx.x * blockDim.x + threadIdx.x) >> 5;
    int lane = threadIdx.x & 31;
    if (row >= M_) return;
    float4 v  = *(const float4*)&x[(size_t)row * D_ + lane * 4];
    float4 v2 = *(const float4*)&g_oproj[(size_t)row * D_ + lane * 4];
    v.x += v2.x; v.y += v2.y; v.z += v2.z; v.w += v2.w;
    ln_store(v, g, b, &g_x1[(size_t)row * D_], lane);
}

__global__ void k_lnt2(const float* __restrict__ g, const float* __restrict__ b) {
    int row = (blockIdx.x * blockDim.x + threadIdx.x) >> 5;
    int lane = threadIdx.x & 31;
    if (row >= M_) return;
    float4 v  = *(const float4*)&g_x1[(size_t)row * D_ + lane * 4];
    float4 v2 = *(const float4*)&g_f2[(size_t)row * D_ + lane * 4];
    v.x += v2.x; v.y += v2.y; v.z += v2.z; v.w += v2.w;
    ln_store(v, g, b, &g_cat[(size_t)row * 256 + 128], lane);
}

__global__ void k_final(const float* __restrict__ x,
                        const float* __restrict__ g, const float* __restrict__ b,
                        float* __restrict__ out) {
    int row = (blockIdx.x * blockDim.x + threadIdx.x) >> 5;
    int lane = threadIdx.x & 31;
    if (row >= M_) return;
    float4 xsp = *(const float4*)&g_cat[(size_t)row * 256 + lane * 4];
    float4 xtp = *(const float4*)&g_cat[(size_t)row * 256 + 128 + lane * 4];
    float4 gt  = *(const float4*)&g_gate[(size_t)row * D_ + lane * 4];
    float4 xv  = *(const float4*)&x[(size_t)row * D_ + lane * 4];
    float4 v = make_float4(gt.x * xsp.x + (1.f - gt.x) * xtp.x + xv.x,
                           gt.y * xsp.y + (1.f - gt.y) * xtp.y + xv.y,
                           gt.z * xsp.z + (1.f - gt.z) * xtp.z + xv.z,
                           gt.w * xsp.w + (1.f - gt.w) * xtp.w + xv.w);
    ln_store(v, g, b, &out[(size_t)row * D_], lane);
}

// ---------------- temporal attention ------------------------------------------------
__global__ void k_attn() {
    int w = blockIdx.x * 4 + (threadIdx.x >> 5);
    int lane = threadIdx.x & 31;
    if (w >= (B_ * N_) * H_) return;
    int bn = w >> 2;
    int h = w & 3;
    float q[8], k[8], v[8];
#pragma unroll
    for (int t = 0; t < 8; t++) {
        size_t base = ((size_t)bn * 8 + t) * 384 + h * 32 + lane;
        q[t] = g_qkv[base];
        k[t] = g_qkv[base + 128];
        v[t] = g_qkv[base + 256];
    }
    const float scale = 0.17677669529663687f;
#pragma unroll
    for (int t = 0; t < 8; t++) {
        float sc[8];
#pragma unroll
        for (int s = 0; s < 8; s++) sc[s] = warp_sum(q[t] * k[s]) * scale;
        float mx = sc[0];
#pragma unroll
        for (int s = 1; s < 8; s++) mx = fmaxf(mx, sc[s]);
        float den = 0.f;
#pragma unroll
        for (int s = 0; s < 8; s++) { sc[s] = __expf(sc[s] - mx); den += sc[s]; }
        float inv = 1.f / den;
        float o = 0.f;
#pragma unroll
        for (int s = 0; s < 8; s++) o += sc[s] * v[s];
        g_attno[((size_t)bn * 8 + t) * D_ + h * 32 + lane] = o * inv;
    }
}

// ---------------- launch ---------------------------------------------------------------
extern "C" void kernel_launch(void* const* d_in, const int* in_sizes, int n_in,
                              void* d_out, int out_size) {
    const float* x      = (const float*)d_in[0];
    const int*   edges  = (const int*)  d_in[1];
    const float* gat_att= (const float*)d_in[4];
    const float* gat_b  = (const float*)d_in[5];
    const float* in_b   = (const float*)d_in[7];
    const float* out_b  = (const float*)d_in[9];
    const float* ffn_b1 = (const float*)d_in[11];
    const float* ffn_b2 = (const float*)d_in[13];
    const float* fus_b  = (const float*)d_in[15];
    const float* lns_g  = (const float*)d_in[16];
    const float* lns_b  = (const float*)d_in[17];
    const float* lnt1_g = (const float*)d_in[18];
    const float* lnt1_b = (const float*)d_in[19];
    const float* lnt2_g = (const float*)d_in[20];
    const float* lnt2_b = (const float*)d_in[21];
    const float* lnf_g  = (const float*)d_in[22];
    const float* lnf_b  = (const float*)d_in[23];
    float* out = (float*)d_out;

    float *p_xlr, *p_qkv, *p_attno, *p_oproj, *p_x1, *p_hid, *p_f2, *p_cat, *p_gate, *p_bxq;
    __nv_bfloat16 *p_Bxq, *p_Bout, *p_Bffn1, *p_Bffn2, *p_Bfus;
    cudaGetSymbolAddress((void**)&p_xlr,   g_xlr);
    cudaGetSymbolAddress((void**)&p_qkv,   g_qkv);
    cudaGetSymbolAddress((void**)&p_attno, g_attno);
    cudaGetSymbolAddress((void**)&p_oproj, g_oproj);
    cudaGetSymbolAddress((void**)&p_x1,    g_x1);
    cudaGetSymbolAddress((void**)&p_hid,   g_hid);
    cudaGetSymbolAddress((void**)&p_f2,    g_f2);
    cudaGetSymbolAddress((void**)&p_cat,   g_cat);
    cudaGetSymbolAddress((void**)&p_gate,  g_gate);
    cudaGetSymbolAddress((void**)&p_bxq,   g_bias_xq);
    cudaGetSymbolAddress((void**)&p_Bxq,   g_Bxq);
    cudaGetSymbolAddress((void**)&p_Bout,  g_Bout);
    cudaGetSymbolAddress((void**)&p_Bffn1, g_Bffn1);
    cudaGetSymbolAddress((void**)&p_Bffn2, g_Bffn2);
    cudaGetSymbolAddress((void**)&p_Bfus,  g_Bfus);

    cudaFuncSetAttribute(hgemm, cudaFuncAttributeMaxDynamicSharedMemorySize, SMEMSZ);

    // prep: CSR + bias + weight splits
    k_init0<<<6, 256>>>(in_b);
    k_scatter<<<E_ / 256, 256>>>(edges);
    k_splitw<<<dim3(256, 7), 256>>>((const float*)d_in[2], (const float*)d_in[3],
                                    (const float*)d_in[6], (const float*)d_in[8],
                                    (const float*)d_in[10], (const float*)d_in[12],
                                    (const float*)d_in[14]);

    // merged spatial+qkv: [xlr | qkv] = x @ [Wl|Wr|Wqkv]
    hgemm<<<dim3(11, 128), 512, SMEMSZ>>>(x, p_Bxq, p_bxq,
                                          p_xlr, 1024, 1024, p_qkv, 384, 128, 1);
    k_gat<<<M_ / 8, 256>>>(gat_att, gat_b, lns_g, lns_b);

    // temporal
    k_attn<<<(B_ * N_ * H_) / 4, 128>>>();
    hgemm<<<dim3(1, 128), 512, SMEMSZ>>>(p_attno, p_Bout, out_b,
                                         p_oproj, 128, 128, p_oproj, 128, 128, 1);
    k_lnt1<<<M_ / 8, 256>>>(x, lnt1_g, lnt1_b);

    // FFN
    hgemm<<<dim3(4, 128), 512, SMEMSZ>>>(p_x1, p_Bffn1, ffn_b1,
                                         p_hid, 512, 512, p_hid, 512, 128, 2);
    hgemm<<<dim3(1, 128), 512, SMEMSZ>>>(p_hid, p_Bffn2, ffn_b2,
                                         p_f2, 128, 128, p_f2, 128, 512, 1);
    k_lnt2<<<M_ / 8, 256>>>(lnt2_g, lnt2_b);

    // fusion
    hgemm<<<dim3(1, 128), 512, SMEMSZ>>>(p_cat, p_Bfus, fus_b,
                                         p_gate, 128, 128, p_gate, 128, 256, 3);
    k_final<<<M_ / 8, 256>>>(x, lnf_g, lnf_b, out);
}

// round 7
// speedup vs baseline: 1.6143x; 1.0021x over previous
#include <cuda_runtime.h>
#include <cuda_bf16.h>
#include <math.h>
#include <stdint.h>

#define B_  2
#define N_  1024
#define T_  8
#define D_  128
#define H_  4
#define E_  8192
#define M_  16384
#define MAXDEG 128

// ---------------- scratch (device globals) ----------------------------------
__device__ __align__(256) float g_xlr[(size_t)M_ * 1024];   // [xl(512)|xr(512)]
__device__ __align__(256) float g_qkv[(size_t)M_ * 384];
__device__ __align__(256) float g_oproj[(size_t)M_ * 128];
__device__ __align__(256) float g_x1[(size_t)M_ * 128];
__device__ __align__(256) float g_f2[(size_t)M_ * 128];
__device__ __align__(256) float g_cat[(size_t)M_ * 256];    // [x_sp | x_tp] fp32
__device__ __align__(256) float g_gate[(size_t)M_ * 128];
// pre-split bf16 A operands: row = [hi(K) | lo(K)]
__device__ __align__(256) __nv_bfloat16 g_xs[(size_t)M_ * 256];
__device__ __align__(256) __nv_bfloat16 g_attnos[(size_t)M_ * 256];
__device__ __align__(256) __nv_bfloat16 g_x1s[(size_t)M_ * 256];
__device__ __align__(256) __nv_bfloat16 g_hids[(size_t)M_ * 1024];
__device__ __align__(256) __nv_bfloat16 g_cats[(size_t)M_ * 512];
// weight splits: row n = [hi(K) | lo(K)] bf16
__device__ __align__(256) __nv_bfloat16 g_Bxq[1408 * 256];  // [Wl|Wr|Wqkv]
__device__ __align__(256) float g_bias_xq[1408];
__device__ __align__(256) __nv_bfloat16 g_Bout[128 * 256];
__device__ __align__(256) __nv_bfloat16 g_Bffn1[512 * 256];
__device__ __align__(256) __nv_bfloat16 g_Bffn2[128 * 1024];
__device__ __align__(256) __nv_bfloat16 g_Bfus[128 * 512];
// CSR
__device__ int g_deg[N_];
__device__ int g_csr[N_ * MAXDEG];

// ---------------- helpers ------------------------------------------------------
__device__ __forceinline__ float warp_sum(float v) {
#pragma unroll
    for (int o = 16; o; o >>= 1) v += __shfl_xor_sync(0xFFFFFFFFu, v, o);
    return v;
}
__device__ __forceinline__ uint32_t smem_u32(const void* p) {
    uint32_t a;
    asm("{ .reg .u64 t; cvta.to.shared.u64 t, %1; cvt.u32.u64 %0, t; }"
        : "=r"(a) : "l"(p));
    return a;
}
#define CP16(dst, src) \
    asm volatile("cp.async.cg.shared.global [%0], [%1], 16;" :: "r"(dst), "l"(src))
#define LDSM4(r0, r1, r2, r3, addr) \
    asm volatile("ldmatrix.sync.aligned.m8n8.x4.shared.b16 {%0,%1,%2,%3}, [%4];" \
        : "=r"(r0), "=r"(r1), "=r"(r2), "=r"(r3) : "r"(addr))
#define LDSM2(r0, r1, addr) \
    asm volatile("ldmatrix.sync.aligned.m8n8.x2.shared.b16 {%0,%1}, [%2];" \
        : "=r"(r0), "=r"(r1) : "r"(addr))

__device__ __forceinline__ void mma16816(float c[4], uint32_t a0, uint32_t a1,
                                         uint32_t a2, uint32_t a3,
                                         uint32_t b0, uint32_t b1) {
    asm volatile(
        "mma.sync.aligned.m16n8k16.row.col.f32.bf16.bf16.f32 "
        "{%0,%1,%2,%3}, {%4,%5,%6,%7}, {%8,%9}, {%0,%1,%2,%3};"
        : "+f"(c[0]), "+f"(c[1]), "+f"(c[2]), "+f"(c[3])
        : "r"(a0), "r"(a1), "r"(a2), "r"(a3), "r"(b0), "r"(b1));
}
__device__ __forceinline__ uint32_t packbf(float x, float y) {
    __nv_bfloat162 h = __floats2bfloat162_rn(x, y);
    return *(uint32_t*)&h;
}
// split pair (a,b) -> hi packed, lo packed
__device__ __forceinline__ void split2(float a, float b, uint32_t& hi, uint32_t& lo) {
    __nv_bfloat16 h0 = __float2bfloat16(a), h1 = __float2bfloat16(b);
    hi = ((uint32_t)__bfloat16_as_ushort(h1) << 16) | __bfloat16_as_ushort(h0);
    lo = packbf(a - __bfloat162float(h0), b - __bfloat162float(h1));
}
// split float4 -> uint2 hi, uint2 lo
__device__ __forceinline__ void split4(float4 v, uint2& hi, uint2& lo) {
    split2(v.x, v.y, hi.x, lo.x);
    split2(v.z, v.w, hi.y, lo.y);
}

// ---------------- init + CSR + bias_xq -------------------------------------------
__global__ void k_init0(const float* __restrict__ in_b) {
    int i = blockIdx.x * blockDim.x + threadIdx.x;
    if (i < N_) { g_deg[i] = 1; g_csr[i * MAXDEG] = i; }   // self loop
    if (i < 1408) g_bias_xq[i] = (i < 1024) ? 0.f : in_b[i - 1024];
}
__global__ void k_scatter(const int* __restrict__ edges) {
    int e = blockIdx.x * blockDim.x + threadIdx.x;
    if (e >= E_) return;
    int s = edges[e], d = edges[E_ + e];
    int pos = atomicAdd(&g_deg[d], 1);
    if (pos < MAXDEG) g_csr[d * MAXDEG + pos] = s;
}

// ---------------- split x ----------------------------------------------------------
__global__ void k_splitx(const float* __restrict__ x) {
    int i = blockIdx.x * 256 + threadIdx.x;     // over M*32
    int row = i >> 5, c4 = (i & 31) * 4;
    float4 v = *(const float4*)&x[(size_t)row * 128 + c4];
    uint2 hi, lo;
    split4(v, hi, lo);
    *(uint2*)&g_xs[(size_t)row * 256 + c4]       = hi;
    *(uint2*)&g_xs[(size_t)row * 256 + 128 + c4] = lo;
}

// ---------------- weight splitting ------------------------------------------------
__global__ void k_splitw(const float* wl, const float* wr, const float* inw,
                         const float* outw, const float* f1w, const float* f2w,
                         const float* fw) {
    int job = blockIdx.y;
    int idx = blockIdx.x * 256 + threadIdx.x;
    const float* W; __nv_bfloat16* Bo; int K, Nw, coff = 0;
    switch (job) {
        case 0: W = wl;   Bo = g_Bxq;   K = 128; Nw = 512; break;
        case 1: W = wr;   Bo = g_Bxq;   K = 128; Nw = 512; coff = 512; break;
        case 2: W = inw;  Bo = g_Bxq;   K = 128; Nw = 384; coff = 1024; break;
        case 3: W = outw; Bo = g_Bout;  K = 128; Nw = 128; break;
        case 4: W = f1w;  Bo = g_Bffn1; K = 128; Nw = 512; break;
        case 5: W = f2w;  Bo = g_Bffn2; K = 512; Nw = 128; break;
        default:W = fw;   Bo = g_Bfus;  K = 256; Nw = 128; break;
    }
    if (idx >= K * Nw) return;
    int k = idx / Nw, n = idx % Nw;
    float v = W[idx];
    __nv_bfloat16 hi = __float2bfloat16(v);
    float lo = v - __bfloat162float(hi);
    size_t o = (size_t)(coff + n) * (size_t)(2 * K) + k;
    Bo[o] = hi;
    Bo[o + K] = __float2bfloat16(lo);
}

// ---------------- bf16x3 mma.sync GEMM ---------------------------------------------
// C = A2 @ W ; both pre-split bf16 (rows x [hi(K)|lo(K)])
// CTA 128x128, 512 thr, 4x4 warps, warp tile 32x32, K-panels 16, 3-stage cp.async.
// mode 1: +bias -> fp32, dual dest (col<N1 -> C1 else C2)
// mode 2: +bias+GELU -> SPLIT bf16 out to Cs (row length 2*Ng)
// mode 3: +bias+sigmoid -> fp32 C1
#define KPAD 24
#define PLANE (128 * KPAD)
#define SMEMSZ (12 * PLANE * 2)

__global__ void __launch_bounds__(512, 1) hgemm(
        const __nv_bfloat16* __restrict__ A2, const __nv_bfloat16* __restrict__ B2,
        const float* __restrict__ bias,
        float* __restrict__ C1, int N1, int s1,
        float* __restrict__ C2, int s2,
        __nv_bfloat16* __restrict__ Cs,
        int Ng, int K, int mode) {
    extern __shared__ __nv_bfloat16 sm[];
    __nv_bfloat16* sAp = sm;               // [3 bufs][2 planes][128][KPAD]
    __nv_bfloat16* sBp = sm + 6 * PLANE;
    int tid = threadIdx.x, wid = tid >> 5, lane = tid & 31;
    int wm = wid >> 2, wn = wid & 3;
    int rowBase = blockIdx.y * 128, colBase = blockIdx.x * 128;
    int nk = K >> 4;

    float acc[2][4][4];
#pragma unroll
    for (int i = 0; i < 2; i++)
#pragma unroll
        for (int j = 0; j < 4; j++)
#pragma unroll
            for (int q = 0; q < 4; q++) acc[i][j][q] = 0.f;

    int lrow = tid >> 2;                    // 0..127
    int lpl = (tid >> 1) & 1;               // plane hi/lo
    int lhf = tid & 1;                      // 16B half of the panel
    const char* Asrc = (const char*)(A2 + (size_t)(rowBase + lrow) * (2 * K) + lpl * K) + lhf * 16;
    const char* Bsrc = (const char*)(B2 + (size_t)(colBase + lrow) * (2 * K) + lpl * K) + lhf * 16;
    uint32_t dApan = smem_u32(sAp) + (((lpl * 128 + lrow) * KPAD) + lhf * 8) * 2;
    uint32_t dBpan = smem_u32(sBp) + (((lpl * 128 + lrow) * KPAD) + lhf * 8) * 2;

    auto ld = [&](int kt, int buf) {
        CP16(dApan + buf * (4 * PLANE), Asrc + kt * 32);
        CP16(dBpan + buf * (4 * PLANE), Bsrc + kt * 32);
        asm volatile("cp.async.commit_group;" ::: "memory");
    };

    ld(0, 0);
    if (nk > 1) ld(1, 1);

    int arf = (lane & 7) + ((lane >> 3) & 1) * 8;
    int acol = ((lane >> 4) & 1) * 8;
    int brf = lane & 7;
    int bcol = ((lane >> 3) & 1) * 8;

    for (int kt = 0; kt < nk; kt++) {
        int buf = kt % 3;
        if (kt + 1 < nk) asm volatile("cp.async.wait_group 1;" ::: "memory");
        else             asm volatile("cp.async.wait_group 0;" ::: "memory");
        __syncthreads();
        if (kt + 2 < nk) ld(kt + 2, (kt + 2) % 3);

        uint32_t ah[2][4], al[2][4], bh[4][2], bl[4][2];
#pragma unroll
        for (int mi = 0; mi < 2; mi++) {
            uint32_t ad = smem_u32(sAp + ((buf * 2 + 0) * 128 + wm * 32 + mi * 16 + arf) * KPAD + acol);
            LDSM4(ah[mi][0], ah[mi][1], ah[mi][2], ah[mi][3], ad);
        }
#pragma unroll
        for (int ni = 0; ni < 4; ni++) {
            uint32_t bd = smem_u32(sBp + ((buf * 2 + 0) * 128 + wn * 32 + ni * 8 + brf) * KPAD + bcol);
            LDSM2(bh[ni][0], bh[ni][1], bd);
        }
#pragma unroll
        for (int mi = 0; mi < 2; mi++)
#pragma unroll
            for (int ni = 0; ni < 4; ni++)
                mma16816(acc[mi][ni], ah[mi][0], ah[mi][1], ah[mi][2], ah[mi][3],
                         bh[ni][0], bh[ni][1]);
#pragma unroll
        for (int mi = 0; mi < 2; mi++) {
            uint32_t ad = smem_u32(sAp + ((buf * 2 + 1) * 128 + wm * 32 + mi * 16 + arf) * KPAD + acol);
            LDSM4(al[mi][0], al[mi][1], al[mi][2], al[mi][3], ad);
        }
#pragma unroll
        for (int ni = 0; ni < 4; ni++) {
            uint32_t bd = smem_u32(sBp + ((buf * 2 + 1) * 128 + wn * 32 + ni * 8 + brf) * KPAD + bcol);
            LDSM2(bl[ni][0], bl[ni][1], bd);
        }
#pragma unroll
        for (int mi = 0; mi < 2; mi++)
#pragma unroll
            for (int ni = 0; ni < 4; ni++) {
                mma16816(acc[mi][ni], ah[mi][0], ah[mi][1], ah[mi][2], ah[mi][3],
                         bl[ni][0], bl[ni][1]);
                mma16816(acc[mi][ni], al[mi][0], al[mi][1], al[mi][2], al[mi][3],
                         bh[ni][0], bh[ni][1]);
            }
    }

    // ---- epilogue ----
    int fr = lane >> 2, fc = (lane & 3) * 2;
#pragma unroll
    for (int mi = 0; mi < 2; mi++) {
        int r0 = rowBase + wm * 32 + mi * 16 + fr;
#pragma unroll
        for (int ni = 0; ni < 4; ni++) {
            int col = colBase + wn * 32 + ni * 8 + fc;
            float b0 = bias[col], b1 = bias[col + 1];
            float v[4] = {acc[mi][ni][0] + b0, acc[mi][ni][1] + b1,
                          acc[mi][ni][2] + b0, acc[mi][ni][3] + b1};
            if (mode == 2) {
#pragma unroll
                for (int q = 0; q < 4; q++)
                    v[q] = 0.5f * v[q] * (1.f + erff(v[q] * 0.70710678118654752f));
                uint32_t h0, l0, h1, l1;
                split2(v[0], v[1], h0, l0);
                split2(v[2], v[3], h1, l1);
                size_t ro0 = (size_t)r0 * (2 * Ng), ro1 = (size_t)(r0 + 8) * (2 * Ng);
                *(uint32_t*)&Cs[ro0 + col]      = h0;
                *(uint32_t*)&Cs[ro0 + Ng + col] = l0;
                *(uint32_t*)&Cs[ro1 + col]      = h1;
                *(uint32_t*)&Cs[ro1 + Ng + col] = l1;
            } else {
                if (mode == 3) {
#pragma unroll
                    for (int q = 0; q < 4; q++) v[q] = 1.f / (1.f + __expf(-v[q]));
                }
                if (col < N1) {
                    *(float2*)&C1[(size_t)r0 * s1 + col]       = make_float2(v[0], v[1]);
                    *(float2*)&C1[(size_t)(r0 + 8) * s1 + col] = make_float2(v[2], v[3]);
                } else {
                    int c2 = col - N1;
                    *(float2*)&C2[(size_t)r0 * s2 + c2]        = make_float2(v[0], v[1]);
                    *(float2*)&C2[(size_t)(r0 + 8) * s2 + c2]  = make_float2(v[2], v[3]);
                }
            }
        }
    }
}

// ---------------- LayerNorm compute (returns normalized vec) ------------------------
__device__ __forceinline__ float4 ln_compute(float4 v, const float* g, const float* b,
                                             int lane) {
    float mean = warp_sum(v.x + v.y + v.z + v.w) * (1.f / 128.f);
    float4 c = make_float4(v.x - mean, v.y - mean, v.z - mean, v.w - mean);
    float var = warp_sum(c.x * c.x + c.y * c.y + c.z * c.z + c.w * c.w) * (1.f / 128.f);
    float rs = rsqrtf(var + 1e-5f);
    float4 gv = *(const float4*)&g[lane * 4];
    float4 bv = *(const float4*)&b[lane * 4];
    return make_float4(c.x * rs * gv.x + bv.x, c.y * rs * gv.y + bv.y,
                       c.z * rs * gv.z + bv.z, c.w * rs * gv.w + bv.w);
}

// ---------------- fused GAT (online softmax, dst-centric) --------------------------
__global__ void k_gat(const float* __restrict__ att, const float* __restrict__ gat_b,
                      const float* __restrict__ lg, const float* __restrict__ lb) {
    int w = (blockIdx.x * blockDim.x + threadIdx.x) >> 5;   // row = (b*N+n)*T+t
    int lane = threadIdx.x & 31;
    if (w >= M_) return;
    int bn = w >> 3;
    int n = bn & (N_ - 1);
    int b = bn >> 10;
    int t = w & 7;

    const float4* xr4 = (const float4*)(g_xlr + (size_t)w * 1024 + 512);
    float4 xr[4], av[4];
#pragma unroll
    for (int h = 0; h < 4; h++) {
        xr[h] = xr4[h * 32 + lane];
        av[h] = ((const float4*)att)[h * 32 + lane];
    }
    float4 acc[4];
#pragma unroll
    for (int h = 0; h < 4; h++) acc[h] = make_float4(0.f, 0.f, 0.f, 0.f);
    float m[4] = {-INFINITY, -INFINITY, -INFINITY, -INFINITY};
    float s[4] = {0.f, 0.f, 0.f, 0.f};

    int deg = g_deg[n];
    if (deg > MAXDEG) deg = MAXDEG;
    const int* clist = g_csr + n * MAXDEG;

    for (int i = 0; i < deg; i++) {
        int src = clist[i];
        const float4* xl4 = (const float4*)(g_xlr + ((size_t)((b * N_ + src) * T_ + t)) * 1024);
        float4 xl[4];
        float lgt[4];
#pragma unroll
        for (int h = 0; h < 4; h++) {
            float4 a = xl4[h * 32 + lane];
            xl[h] = a;
            float v0 = a.x + xr[h].x; v0 = v0 > 0.f ? v0 : 0.2f * v0;
            float v1 = a.y + xr[h].y; v1 = v1 > 0.f ? v1 : 0.2f * v1;
            float v2 = a.z + xr[h].z; v2 = v2 > 0.f ? v2 : 0.2f * v2;
            float v3 = a.w + xr[h].w; v3 = v3 > 0.f ? v3 : 0.2f * v3;
            lgt[h] = warp_sum(av[h].x * v0 + av[h].y * v1 + av[h].z * v2 + av[h].w * v3);
        }
#pragma unroll
        for (int h = 0; h < 4; h++) {
            float nm = fmaxf(m[h], lgt[h]);
            float e0 = __expf(m[h] - nm);
            float e1 = __expf(lgt[h] - nm);
            s[h] = s[h] * e0 + e1;
            acc[h].x = acc[h].x * e0 + e1 * xl[h].x;
            acc[h].y = acc[h].y * e0 + e1 * xl[h].y;
            acc[h].z = acc[h].z * e0 + e1 * xl[h].z;
            acc[h].w = acc[h].w * e0 + e1 * xl[h].w;
            m[h] = nm;
        }
    }

    float4 o = make_float4(0.f, 0.f, 0.f, 0.f);
#pragma unroll
    for (int h = 0; h < 4; h++) {
        float r = 0.25f / s[h];
        o.x += acc[h].x * r; o.y += acc[h].y * r;
        o.z += acc[h].z * r; o.w += acc[h].w * r;
    }
    float4 gb = *(const float4*)&gat_b[lane * 4];
    o.x += gb.x; o.y += gb.y; o.z += gb.z; o.w += gb.w;

    float4 r4 = ln_compute(o, lg, lb, lane);
    *(float4*)&g_cat[(size_t)w * 256 + lane * 4] = r4;
    uint2 hi, lo;
    split4(r4, hi, lo);
    *(uint2*)&g_cats[(size_t)w * 512 + lane * 4]       = hi;
    *(uint2*)&g_cats[(size_t)w * 512 + 256 + lane * 4] = lo;
}

// ---------------- residual LNs ------------------------------------------------------
__global__ void k_lnt1(const float* __restrict__ x,
                       const float* __restrict__ g, const float* __restrict__ b) {
    int row = (blockIdx.x * blockDim.x + threadIdx.x) >> 5;
    int lane = threadIdx.x & 31;
    if (row >= M_) return;
    float4 v  = *(const float4*)&x[(size_t)row * D_ + lane * 4];
    float4 v2 = *(const float4*)&g_oproj[(size_t)row * D_ + lane * 4];
    v.x += v2.x; v.y += v2.y; v.z += v2.z; v.w += v2.w;
    float4 r4 = ln_compute(v, g, b, lane);
    *(float4*)&g_x1[(size_t)row * D_ + lane * 4] = r4;
    uint2 hi, lo;
    split4(r4, hi, lo);
    *(uint2*)&g_x1s[(size_t)row * 256 + lane * 4]       = hi;
    *(uint2*)&g_x1s[(size_t)row * 256 + 128 + lane * 4] = lo;
}

__global__ void k_lnt2(const float* __restrict__ g, const float* __restrict__ b) {
    int row = (blockIdx.x * blockDim.x + threadIdx.x) >> 5;
    int lane = threadIdx.x & 31;
    if (row >= M_) return;
    float4 v  = *(const float4*)&g_x1[(size_t)row * D_ + lane * 4];
    float4 v2 = *(const float4*)&g_f2[(size_t)row * D_ + lane * 4];
    v.x += v2.x; v.y += v2.y; v.z += v2.z; v.w += v2.w;
    float4 r4 = ln_compute(v, g, b, lane);
    *(float4*)&g_cat[(size_t)row * 256 + 128 + lane * 4] = r4;
    uint2 hi, lo;
    split4(r4, hi, lo);
    *(uint2*)&g_cats[(size_t)row * 512 + 128 + lane * 4] = hi;
    *(uint2*)&g_cats[(size_t)row * 512 + 384 + lane * 4] = lo;
}

__global__ void k_final(const float* __restrict__ x,
                        const float* __restrict__ g, const float* __restrict__ b,
                        float* __restrict__ out) {
    int row = (blockIdx.x * blockDim.x + threadIdx.x) >> 5;
    int lane = threadIdx.x & 31;
    if (row >= M_) return;
    float4 xsp = *(const float4*)&g_cat[(size_t)row * 256 + lane * 4];
    float4 xtp = *(const float4*)&g_cat[(size_t)row * 256 + 128 + lane * 4];
    float4 gt  = *(const float4*)&g_gate[(size_t)row * D_ + lane * 4];
    float4 xv  = *(const float4*)&x[(size_t)row * D_ + lane * 4];
    float4 v = make_float4(gt.x * xsp.x + (1.f - gt.x) * xtp.x + xv.x,
                           gt.y * xsp.y + (1.f - gt.y) * xtp.y + xv.y,
                           gt.z * xsp.z + (1.f - gt.z) * xtp.z + xv.z,
                           gt.w * xsp.w + (1.f - gt.w) * xtp.w + xv.w);
    float4 r4 = ln_compute(v, g, b, lane);
    *(float4*)&out[(size_t)row * D_ + lane * 4] = r4;
}

// ---------------- temporal attention ------------------------------------------------
__global__ void k_attn() {
    int w = blockIdx.x * 4 + (threadIdx.x >> 5);
    int lane = threadIdx.x & 31;
    if (w >= (B_ * N_) * H_) return;
    int bn = w >> 2;
    int h = w & 3;
    float q[8], k[8], v[8];
#pragma unroll
    for (int t = 0; t < 8; t++) {
        size_t base = ((size_t)bn * 8 + t) * 384 + h * 32 + lane;
        q[t] = g_qkv[base];
        k[t] = g_qkv[base + 128];
        v[t] = g_qkv[base + 256];
    }
    const float scale = 0.17677669529663687f;
#pragma unroll
    for (int t = 0; t < 8; t++) {
        float sc[8];
#pragma unroll
        for (int s = 0; s < 8; s++) sc[s] = warp_sum(q[t] * k[s]) * scale;
        float mx = sc[0];
#pragma unroll
        for (int s = 1; s < 8; s++) mx = fmaxf(mx, sc[s]);
        float den = 0.f;
#pragma unroll
        for (int s = 0; s < 8; s++) { sc[s] = __expf(sc[s] - mx); den += sc[s]; }
        float inv = 1.f / den;
        float o = 0.f;
#pragma unroll
        for (int s = 0; s < 8; s++) o += sc[s] * v[s];
        o *= inv;
        __nv_bfloat16 hb = __float2bfloat16(o);
        float lof = o - __bfloat162float(hb);
        size_t ro = ((size_t)bn * 8 + t) * 256 + h * 32 + lane;
        g_attnos[ro]       = hb;
        g_attnos[ro + 128] = __float2bfloat16(lof);
    }
}

// ---------------- launch ---------------------------------------------------------------
extern "C" void kernel_launch(void* const* d_in, const int* in_sizes, int n_in,
                              void* d_out, int out_size) {
    const float* x      = (const float*)d_in[0];
    const int*   edges  = (const int*)  d_in[1];
    const float* gat_att= (const float*)d_in[4];
    const float* gat_b  = (const float*)d_in[5];
    const float* in_b   = (const float*)d_in[7];
    const float* out_b  = (const float*)d_in[9];
    const float* ffn_b1 = (const float*)d_in[11];
    const float* ffn_b2 = (const float*)d_in[13];
    const float* fus_b  = (const float*)d_in[15];
    const float* lns_g  = (const float*)d_in[16];
    const float* lns_b  = (const float*)d_in[17];
    const float* lnt1_g = (const float*)d_in[18];
    const float* lnt1_b = (const float*)d_in[19];
    const float* lnt2_g = (const float*)d_in[20];
    const float* lnt2_b = (const float*)d_in[21];
    const float* lnf_g  = (const float*)d_in[22];
    const float* lnf_b  = (const float*)d_in[23];
    float* out = (float*)d_out;

    float *p_xlr, *p_qkv, *p_oproj, *p_x1, *p_f2, *p_cat, *p_gate, *p_bxq;
    __nv_bfloat16 *p_Bxq, *p_Bout, *p_Bffn1, *p_Bffn2, *p_Bfus;
    __nv_bfloat16 *p_xs, *p_attnos, *p_x1s, *p_hids, *p_cats;
    cudaGetSymbolAddress((void**)&p_xlr,    g_xlr);
    cudaGetSymbolAddress((void**)&p_qkv,    g_qkv);
    cudaGetSymbolAddress((void**)&p_oproj,  g_oproj);
    cudaGetSymbolAddress((void**)&p_x1,     g_x1);
    cudaGetSymbolAddress((void**)&p_f2,     g_f2);
    cudaGetSymbolAddress((void**)&p_cat,    g_cat);
    cudaGetSymbolAddress((void**)&p_gate,   g_gate);
    cudaGetSymbolAddress((void**)&p_bxq,    g_bias_xq);
    cudaGetSymbolAddress((void**)&p_Bxq,    g_Bxq);
    cudaGetSymbolAddress((void**)&p_Bout,   g_Bout);
    cudaGetSymbolAddress((void**)&p_Bffn1,  g_Bffn1);
    cudaGetSymbolAddress((void**)&p_Bffn2,  g_Bffn2);
    cudaGetSymbolAddress((void**)&p_Bfus,   g_Bfus);
    cudaGetSymbolAddress((void**)&p_xs,     g_xs);
    cudaGetSymbolAddress((void**)&p_attnos, g_attnos);
    cudaGetSymbolAddress((void**)&p_x1s,    g_x1s);
    cudaGetSymbolAddress((void**)&p_hids,   g_hids);
    cudaGetSymbolAddress((void**)&p_cats,   g_cats);

    cudaFuncSetAttribute(hgemm, cudaFuncAttributeMaxDynamicSharedMemorySize, SMEMSZ);

    // prep: CSR + bias + splits
    k_init0<<<6, 256>>>(in_b);
    k_scatter<<<E_ / 256, 256>>>(edges);
    k_splitw<<<dim3(256, 7), 256>>>((const float*)d_in[2], (const float*)d_in[3],
                                    (const float*)d_in[6], (const float*)d_in[8],
                                    (const float*)d_in[10], (const float*)d_in[12],
                                    (const float*)d_in[14]);
    k_splitx<<<M_ * 32 / 256, 256>>>(x);

    // merged spatial+qkv: [xlr | qkv] = x @ [Wl|Wr|Wqkv]
    hgemm<<<dim3(11, 128), 512, SMEMSZ>>>(p_xs, p_Bxq, p_bxq,
                                          p_xlr, 1024, 1024, p_qkv, 384,
                                          nullptr, 1408, 128, 1);
    k_gat<<<M_ / 8, 256>>>(gat_att, gat_b, lns_g, lns_b);

    // temporal
    k_attn<<<(B_ * N_ * H_) / 4, 128>>>();
    hgemm<<<dim3(1, 128), 512, SMEMSZ>>>(p_attnos, p_Bout, out_b,
                                         p_oproj, 128, 128, p_oproj, 128,
                                         nullptr, 128, 128, 1);
    k_lnt1<<<M_ / 8, 256>>>(x, lnt1_g, lnt1_b);

    // FFN: hid (split bf16) = gelu(x1 @ W1 + b1); f2 = hid @ W2 + b2
    hgemm<<<dim3(4, 128), 512, SMEMSZ>>>(p_x1s, p_Bffn1, ffn_b1,
                                         nullptr, 512, 512, nullptr, 512,
                                         p_hids, 512, 128, 2);
    hgemm<<<dim3(1, 128), 512, SMEMSZ>>>(p_hids, p_Bffn2, ffn_b2,
                                         p_f2, 128, 128, p_f2, 128,
                                         nullptr, 128, 512, 1);
    k_lnt2<<<M_ / 8, 256>>>(lnt2_g, lnt2_b);

    // fusion
    hgemm<<<dim3(1, 128), 512, SMEMSZ>>>(p_cats, p_Bfus, fus_b,
                                         p_gate, 128, 128, p_gate, 128,
                                         nullptr, 128, 256, 3);
    k_final<<<M_ / 8, 256>>>(x, lnf_g, lnf_b, out);
}

// round 8
// speedup vs baseline: 1.9489x; 1.2073x over previous
#include <cuda_runtime.h>
#include <cuda_bf16.h>
#include <math.h>
#include <stdint.h>

#define B_  2
#define N_  1024
#define T_  8
#define D_  128
#define H_  4
#define E_  8192
#define M_  16384
#define MAXDEG 128

// ---------------- scratch (device globals) ----------------------------------
__device__ __align__(256) float g_xlr[(size_t)M_ * 1024];   // [xl(512)|xr(512)]
__device__ __align__(256) float g_qkv[(size_t)M_ * 384];
__device__ __align__(256) float g_attno[(size_t)M_ * 128];
__device__ __align__(256) float g_oproj[(size_t)M_ * 128];
__device__ __align__(256) float g_x1[(size_t)M_ * 128];
__device__ __align__(256) float g_hid[(size_t)M_ * 512];
__device__ __align__(256) float g_f2[(size_t)M_ * 128];
__device__ __align__(256) float g_cat[(size_t)M_ * 256];    // [x_sp | x_tp]
__device__ __align__(256) float g_gate[(size_t)M_ * 128];
// packed tf32 weights, [n][k] layout (pre-rounded via cvt.rna)
__device__ __align__(256) float g_Bxq[1408 * 128];          // [Wl|Wr|Wqkv]
__device__ __align__(256) float g_bias_xq[1408];
__device__ __align__(256) float g_Bout[128 * 128];
__device__ __align__(256) float g_Bffn1[512 * 128];
__device__ __align__(256) float g_Bffn2[128 * 512];
__device__ __align__(256) float g_Bfus[128 * 256];
// CSR
__device__ int g_deg[N_];
__device__ int g_csr[N_ * MAXDEG];

// ---------------- helpers ------------------------------------------------------
__device__ __forceinline__ float warp_sum(float v) {
#pragma unroll
    for (int o = 16; o; o >>= 1) v += __shfl_xor_sync(0xFFFFFFFFu, v, o);
    return v;
}
__device__ __forceinline__ uint32_t smem_u32(const void* p) {
    uint32_t a;
    asm("{ .reg .u64 t; cvta.to.shared.u64 t, %1; cvt.u32.u64 %0, t; }"
        : "=r"(a) : "l"(p));
    return a;
}
#define CP16(dst, src) \
    asm volatile("cp.async.cg.shared.global [%0], [%1], 16;" :: "r"(dst), "l"(src))
#define CVT_TF32(u, f) asm("cvt.rna.tf32.f32 %0, %1;" : "=r"(u) : "f"(f))

__device__ __forceinline__ void mma_tf32(float c[4], const uint32_t a[4],
                                         const uint32_t b[2]) {
    asm volatile(
        "mma.sync.aligned.m16n8k8.row.col.f32.tf32.tf32.f32 "
        "{%0,%1,%2,%3}, {%4,%5,%6,%7}, {%8,%9}, {%0,%1,%2,%3};"
        : "+f"(c[0]), "+f"(c[1]), "+f"(c[2]), "+f"(c[3])
        : "r"(a[0]), "r"(a[1]), "r"(a[2]), "r"(a[3]), "r"(b[0]), "r"(b[1]));
}

// ---------------- init + CSR + bias_xq -------------------------------------------
__global__ void k_init0(const float* __restrict__ in_b) {
    int i = blockIdx.x * blockDim.x + threadIdx.x;
    if (i < N_) { g_deg[i] = 1; g_csr[i * MAXDEG] = i; }   // self loop
    if (i < 1408) g_bias_xq[i] = (i < 1024) ? 0.f : in_b[i - 1024];
}
__global__ void k_scatter(const int* __restrict__ edges) {
    int e = blockIdx.x * blockDim.x + threadIdx.x;
    if (e >= E_) return;
    int s = edges[e], d = edges[E_ + e];
    int pos = atomicAdd(&g_deg[d], 1);
    if (pos < MAXDEG) g_csr[d * MAXDEG + pos] = s;
}

// ---------------- weight packing: transpose to [n][k], round to tf32 -------------
__global__ void k_packw(const float* wl, const float* wr, const float* inw,
                        const float* outw, const float* f1w, const float* f2w,
                        const float* fw) {
    int job = blockIdx.y;
    int idx = blockIdx.x * 256 + threadIdx.x;
    const float* W; float* Bo; int K, Nw, coff = 0;
    switch (job) {
        case 0: W = wl;   Bo = g_Bxq;   K = 128; Nw = 512; break;
        case 1: W = wr;   Bo = g_Bxq;   K = 128; Nw = 512; coff = 512; break;
        case 2: W = inw;  Bo = g_Bxq;   K = 128; Nw = 384; coff = 1024; break;
        case 3: W = outw; Bo = g_Bout;  K = 128; Nw = 128; break;
        case 4: W = f1w;  Bo = g_Bffn1; K = 128; Nw = 512; break;
        case 5: W = f2w;  Bo = g_Bffn2; K = 512; Nw = 128; break;
        default:W = fw;   Bo = g_Bfus;  K = 256; Nw = 128; break;
    }
    if (idx >= K * Nw) return;
    int k = idx / Nw, n = idx % Nw;
    uint32_t u;
    CVT_TF32(u, W[idx]);
    Bo[(size_t)(coff + n) * K + k] = __uint_as_float(u);
}

// ---------------- tf32 mma.sync GEMM -----------------------------------------------
// C = A(fp32 MxK) @ W(tf32 packed [n][k])
// CTA tile 64x128, 256 thr, 2x4 warps, warp tile 32x32, K-panels 16, 3-stage.
// mode 1: +bias; 2: +bias+GELU; 3: +bias+sigmoid. Dual dest: col<N1 -> C1 else C2.
#define KP 20
#define APLANE (64 * KP)
#define BPLANE (128 * KP)
#define SMEMSZ ((APLANE + BPLANE) * 3 * 4)

__global__ void __launch_bounds__(256, 2) hgemm(
        const float* __restrict__ A, const float* __restrict__ Bp,
        const float* __restrict__ bias,
        float* __restrict__ C1, int N1, int s1,
        float* __restrict__ C2, int s2,
        int K, int mode) {
    extern __shared__ float sm[];
    float* sA = sm;                    // [3][64][KP]
    float* sB = sm + 3 * APLANE;       // [3][128][KP]
    int tid = threadIdx.x, wid = tid >> 5, lane = tid & 31;
    int wm = wid >> 2, wn = wid & 3;
    int rowBase = blockIdx.y * 64, colBase = blockIdx.x * 128;
    int nk = K >> 4;

    float acc[2][4][4];
#pragma unroll
    for (int i = 0; i < 2; i++)
#pragma unroll
        for (int j = 0; j < 4; j++)
#pragma unroll
            for (int q = 0; q < 4; q++) acc[i][j][q] = 0.f;

    // loaders: A 64x16 f32 (1 CP16/thr), B 128x16 f32 (2 CP16/thr)
    int ar = tid >> 2, aq = tid & 3;
    int br = tid >> 1, bq = (tid & 1) * 2;
    const char* Asrc = (const char*)(A + (size_t)(rowBase + ar) * K + aq * 4);
    const char* Bsrc = (const char*)(Bp + (size_t)(colBase + br) * K + bq * 4);
    uint32_t dA = smem_u32(sA) + (uint32_t)(ar * KP + aq * 4) * 4;
    uint32_t dB = smem_u32(sB) + (uint32_t)(br * KP + bq * 4) * 4;

    auto ld = [&](int kt, int buf) {
        CP16(dA + buf * (APLANE * 4), Asrc + (size_t)kt * 64);
        CP16(dB + buf * (BPLANE * 4), Bsrc + (size_t)kt * 64);
        CP16(dB + buf * (BPLANE * 4) + 16, Bsrc + (size_t)kt * 64 + 16);
        asm volatile("cp.async.commit_group;" ::: "memory");
    };

    ld(0, 0);
    if (nk > 1) ld(1, 1);

    // per-warp fragment base pointers
    int fr = lane >> 2, fq = lane & 3;
    const float* awp = sA + (wm * 32 + fr) * KP + fq;
    const float* bwp = sB + (wn * 32 + fr) * KP + fq;

    for (int kt = 0; kt < nk; kt++) {
        int buf = kt % 3;
        if (kt + 1 < nk) asm volatile("cp.async.wait_group 1;" ::: "memory");
        else             asm volatile("cp.async.wait_group 0;" ::: "memory");
        __syncthreads();
        if (kt + 2 < nk) ld(kt + 2, (kt + 2) % 3);

        const float* aw = awp + buf * APLANE;
        const float* bw = bwp + buf * BPLANE;
#pragma unroll
        for (int k8 = 0; k8 < 2; k8++) {
            uint32_t ua[2][4], ub[4][2];
#pragma unroll
            for (int mi = 0; mi < 2; mi++) {
                const float* ap = aw + mi * (16 * KP) + k8 * 8;
                CVT_TF32(ua[mi][0], ap[0]);
                CVT_TF32(ua[mi][1], ap[8 * KP]);
                CVT_TF32(ua[mi][2], ap[4]);
                CVT_TF32(ua[mi][3], ap[8 * KP + 4]);
            }
#pragma unroll
            for (int ni = 0; ni < 4; ni++) {
                const float* bp = bw + ni * (8 * KP) + k8 * 8;
                ub[ni][0] = __float_as_uint(bp[0]);
                ub[ni][1] = __float_as_uint(bp[4]);
            }
#pragma unroll
            for (int mi = 0; mi < 2; mi++)
#pragma unroll
                for (int ni = 0; ni < 4; ni++)
                    mma_tf32(acc[mi][ni], ua[mi], ub[ni]);
        }
    }

    // ---- epilogue ----
    int fc2 = (lane & 3) * 2;
#pragma unroll
    for (int mi = 0; mi < 2; mi++) {
        int r0 = rowBase + wm * 32 + mi * 16 + fr;
#pragma unroll
        for (int ni = 0; ni < 4; ni++) {
            int col = colBase + wn * 32 + ni * 8 + fc2;
            float b0 = bias[col], b1 = bias[col + 1];
            float v[4] = {acc[mi][ni][0] + b0, acc[mi][ni][1] + b1,
                          acc[mi][ni][2] + b0, acc[mi][ni][3] + b1};
            if (mode == 2) {
#pragma unroll
                for (int q = 0; q < 4; q++)
                    v[q] = 0.5f * v[q] * (1.f + erff(v[q] * 0.70710678118654752f));
            } else if (mode == 3) {
#pragma unroll
                for (int q = 0; q < 4; q++) v[q] = 1.f / (1.f + __expf(-v[q]));
            }
            if (col < N1) {
                *(float2*)&C1[(size_t)r0 * s1 + col]       = make_float2(v[0], v[1]);
                *(float2*)&C1[(size_t)(r0 + 8) * s1 + col] = make_float2(v[2], v[3]);
            } else {
                int c2 = col - N1;
                *(float2*)&C2[(size_t)r0 * s2 + c2]        = make_float2(v[0], v[1]);
                *(float2*)&C2[(size_t)(r0 + 8) * s2 + c2]  = make_float2(v[2], v[3]);
            }
        }
    }
}

// ---------------- LayerNorm compute ---------------------------------------------
__device__ __forceinline__ float4 ln_compute(float4 v, const float* g, const float* b,
                                             int lane) {
    float mean = warp_sum(v.x + v.y + v.z + v.w) * (1.f / 128.f);
    float4 c = make_float4(v.x - mean, v.y - mean, v.z - mean, v.w - mean);
    float var = warp_sum(c.x * c.x + c.y * c.y + c.z * c.z + c.w * c.w) * (1.f / 128.f);
    float rs = rsqrtf(var + 1e-5f);
    float4 gv = *(const float4*)&g[lane * 4];
    float4 bv = *(const float4*)&b[lane * 4];
    return make_float4(c.x * rs * gv.x + bv.x, c.y * rs * gv.y + bv.y,
                       c.z * rs * gv.z + bv.z, c.w * rs * gv.w + bv.w);
}

// ---------------- fused GAT (online softmax, dst-centric) --------------------------
__global__ void k_gat(const float* __restrict__ att, const float* __restrict__ gat_b,
                      const float* __restrict__ lg, const float* __restrict__ lb) {
    int w = (blockIdx.x * blockDim.x + threadIdx.x) >> 5;   // row = (b*N+n)*T+t
    int lane = threadIdx.x & 31;
    if (w >= M_) return;
    int bn = w >> 3;
    int n = bn & (N_ - 1);
    int b = bn >> 10;
    int t = w & 7;

    const float4* xr4 = (const float4*)(g_xlr + (size_t)w * 1024 + 512);
    float4 xr[4], av[4];
#pragma unroll
    for (int h = 0; h < 4; h++) {
        xr[h] = xr4[h * 32 + lane];
        av[h] = ((const float4*)att)[h * 32 + lane];
    }
    float4 acc[4];
#pragma unroll
    for (int h = 0; h < 4; h++) acc[h] = make_float4(0.f, 0.f, 0.f, 0.f);
    float m[4] = {-INFINITY, -INFINITY, -INFINITY, -INFINITY};
    float s[4] = {0.f, 0.f, 0.f, 0.f};

    int deg = g_deg[n];
    if (deg > MAXDEG) deg = MAXDEG;
    const int* clist = g_csr + n * MAXDEG;

    for (int i = 0; i < deg; i++) {
        int src = clist[i];
        const float4* xl4 = (const float4*)(g_xlr + ((size_t)((b * N_ + src) * T_ + t)) * 1024);
        float4 xl[4];
        float lgt[4];
#pragma unroll
        for (int h = 0; h < 4; h++) {
            float4 a = xl4[h * 32 + lane];
            xl[h] = a;
            float v0 = a.x + xr[h].x; v0 = v0 > 0.f ? v0 : 0.2f * v0;
            float v1 = a.y + xr[h].y; v1 = v1 > 0.f ? v1 : 0.2f * v1;
            float v2 = a.z + xr[h].z; v2 = v2 > 0.f ? v2 : 0.2f * v2;
            float v3 = a.w + xr[h].w; v3 = v3 > 0.f ? v3 : 0.2f * v3;
            lgt[h] = warp_sum(av[h].x * v0 + av[h].y * v1 + av[h].z * v2 + av[h].w * v3);
        }
#pragma unroll
        for (int h = 0; h < 4; h++) {
            float nm = fmaxf(m[h], lgt[h]);
            float e0 = __expf(m[h] - nm);
            float e1 = __expf(lgt[h] - nm);
            s[h] = s[h] * e0 + e1;
            acc[h].x = acc[h].x * e0 + e1 * xl[h].x;
            acc[h].y = acc[h].y * e0 + e1 * xl[h].y;
            acc[h].z = acc[h].z * e0 + e1 * xl[h].z;
            acc[h].w = acc[h].w * e0 + e1 * xl[h].w;
            m[h] = nm;
        }
    }

    float4 o = make_float4(0.f, 0.f, 0.f, 0.f);
#pragma unroll
    for (int h = 0; h < 4; h++) {
        float r = 0.25f / s[h];
        o.x += acc[h].x * r; o.y += acc[h].y * r;
        o.z += acc[h].z * r; o.w += acc[h].w * r;
    }
    float4 gb = *(const float4*)&gat_b[lane * 4];
    o.x += gb.x; o.y += gb.y; o.z += gb.z; o.w += gb.w;

    float4 r4 = ln_compute(o, lg, lb, lane);
    *(float4*)&g_cat[(size_t)w * 256 + lane * 4] = r4;
}

// ---------------- residual LNs ------------------------------------------------------
__global__ void k_lnt1(const float* __restrict__ x,
                       const float* __restrict__ g, const float* __restrict__ b) {
    int row = (blockIdx.x * blockDim.x + threadIdx.x) >> 5;
    int lane = threadIdx.x & 31;
    if (row >= M_) return;
    float4 v  = *(const float4*)&x[(size_t)row * D_ + lane * 4];
    float4 v2 = *(const float4*)&g_oproj[(size_t)row * D_ + lane * 4];
    v.x += v2.x; v.y += v2.y; v.z += v2.z; v.w += v2.w;
    float4 r4 = ln_compute(v, g, b, lane);
    *(float4*)&g_x1[(size_t)row * D_ + lane * 4] = r4;
}

__global__ void k_lnt2(const float* __restrict__ g, const float* __restrict__ b) {
    int row = (blockIdx.x * blockDim.x + threadIdx.x) >> 5;
    int lane = threadIdx.x & 31;
    if (row >= M_) return;
    float4 v  = *(const float4*)&g_x1[(size_t)row * D_ + lane * 4];
    float4 v2 = *(const float4*)&g_f2[(size_t)row * D_ + lane * 4];
    v.x += v2.x; v.y += v2.y; v.z += v2.z; v.w += v2.w;
    float4 r4 = ln_compute(v, g, b, lane);
    *(float4*)&g_cat[(size_t)row * 256 + 128 + lane * 4] = r4;
}

__global__ void k_final(const float* __restrict__ x,
                        const float* __restrict__ g, const float* __restrict__ b,
                        float* __restrict__ out) {
    int row = (blockIdx.x * blockDim.x + threadIdx.x) >> 5;
    int lane = threadIdx.x & 31;
    if (row >= M_) return;
    float4 xsp = *(const float4*)&g_cat[(size_t)row * 256 + lane * 4];
    float4 xtp = *(const float4*)&g_cat[(size_t)row * 256 + 128 + lane * 4];
    float4 gt  = *(const float4*)&g_gate[(size_t)row * D_ + lane * 4];
    float4 xv  = *(const float4*)&x[(size_t)row * D_ + lane * 4];
    float4 v = make_float4(gt.x * xsp.x + (1.f - gt.x) * xtp.x + xv.x,
                           gt.y * xsp.y + (1.f - gt.y) * xtp.y + xv.y,
                           gt.z * xsp.z + (1.f - gt.z) * xtp.z + xv.z,
                           gt.w * xsp.w + (1.f - gt.w) * xtp.w + xv.w);
    float4 r4 = ln_compute(v, g, b, lane);
    *(float4*)&out[(size_t)row * D_ + lane * 4] = r4;
}

// ---------------- temporal attention ------------------------------------------------
__global__ void k_attn() {
    int w = blockIdx.x * 4 + (threadIdx.x >> 5);
    int lane = threadIdx.x & 31;
    if (w >= (B_ * N_) * H_) return;
    int bn = w >> 2;
    int h = w & 3;
    float q[8], k[8], v[8];
#pragma unroll
    for (int t = 0; t < 8; t++) {
        size_t base = ((size_t)bn * 8 + t) * 384 + h * 32 + lane;
        q[t] = g_qkv[base];
        k[t] = g_qkv[base + 128];
        v[t] = g_qkv[base + 256];
    }
    const float scale = 0.17677669529663687f;
#pragma unroll
    for (int t = 0; t < 8; t++) {
        float sc[8];
#pragma unroll
        for (int s = 0; s < 8; s++) sc[s] = warp_sum(q[t] * k[s]) * scale;
        float mx = sc[0];
#pragma unroll
        for (int s = 1; s < 8; s++) mx = fmaxf(mx, sc[s]);
        float den = 0.f;
#pragma unroll
        for (int s = 0; s < 8; s++) { sc[s] = __expf(sc[s] - mx); den += sc[s]; }
        float inv = 1.f / den;
        float o = 0.f;
#pragma unroll
        for (int s = 0; s < 8; s++) o += sc[s] * v[s];
        g_attno[((size_t)bn * 8 + t) * D_ + h * 32 + lane] = o * inv;
    }
}

// ---------------- launch ---------------------------------------------------------------
extern "C" void kernel_launch(void* const* d_in, const int* in_sizes, int n_in,
                              void* d_out, int out_size) {
    const float* x      = (const float*)d_in[0];
    const int*   edges  = (const int*)  d_in[1];
    const float* gat_att= (const float*)d_in[4];
    const float* gat_b  = (const float*)d_in[5];
    const float* in_b   = (const float*)d_in[7];
    const float* out_b  = (const float*)d_in[9];
    const float* ffn_b1 = (const float*)d_in[11];
    const float* ffn_b2 = (const float*)d_in[13];
    const float* fus_b  = (const float*)d_in[15];
    const float* lns_g  = (const float*)d_in[16];
    const float* lns_b  = (const float*)d_in[17];
    const float* lnt1_g = (const float*)d_in[18];
    const float* lnt1_b = (const float*)d_in[19];
    const float* lnt2_g = (const float*)d_in[20];
    const float* lnt2_b = (const float*)d_in[21];
    const float* lnf_g  = (const float*)d_in[22];
    const float* lnf_b  = (const float*)d_in[23];
    float* out = (float*)d_out;

    float *p_xlr, *p_qkv, *p_attno, *p_oproj, *p_x1, *p_hid, *p_f2, *p_cat, *p_gate;
    float *p_bxq, *p_Bxq, *p_Bout, *p_Bffn1, *p_Bffn2, *p_Bfus;
    cudaGetSymbolAddress((void**)&p_xlr,   g_xlr);
    cudaGetSymbolAddress((void**)&p_qkv,   g_qkv);
    cudaGetSymbolAddress((void**)&p_attno, g_attno);
    cudaGetSymbolAddress((void**)&p_oproj, g_oproj);
    cudaGetSymbolAddress((void**)&p_x1,    g_x1);
    cudaGetSymbolAddress((void**)&p_hid,   g_hid);
    cudaGetSymbolAddress((void**)&p_f2,    g_f2);
    cudaGetSymbolAddress((void**)&p_cat,   g_cat);
    cudaGetSymbolAddress((void**)&p_gate,  g_gate);
    cudaGetSymbolAddress((void**)&p_bxq,   g_bias_xq);
    cudaGetSymbolAddress((void**)&p_Bxq,   g_Bxq);
    cudaGetSymbolAddress((void**)&p_Bout,  g_Bout);
    cudaGetSymbolAddress((void**)&p_Bffn1, g_Bffn1);
    cudaGetSymbolAddress((void**)&p_Bffn2, g_Bffn2);
    cudaGetSymbolAddress((void**)&p_Bfus,  g_Bfus);

    cudaFuncSetAttribute(hgemm, cudaFuncAttributeMaxDynamicSharedMemorySize, SMEMSZ);

    // prep
    k_init0<<<6, 256>>>(in_b);
    k_scatter<<<E_ / 256, 256>>>(edges);
    k_packw<<<dim3(256, 7), 256>>>((const float*)d_in[2], (const float*)d_in[3],
                                   (const float*)d_in[6], (const float*)d_in[8],
                                   (const float*)d_in[10], (const float*)d_in[12],
                                   (const float*)d_in[14]);

    // merged spatial+qkv: [xlr | qkv] = x @ [Wl|Wr|Wqkv]
    hgemm<<<dim3(11, 256), 256, SMEMSZ>>>(x, p_Bxq, p_bxq,
                                          p_xlr, 1024, 1024, p_qkv, 384, 128, 1);
    k_gat<<<M_ / 8, 256>>>(gat_att, gat_b, lns_g, lns_b);

    // temporal
    k_attn<<<(B_ * N_ * H_) / 4, 128>>>();
    hgemm<<<dim3(1, 256), 256, SMEMSZ>>>(p_attno, p_Bout, out_b,
                                         p_oproj, 128, 128, p_oproj, 128, 128, 1);
    k_lnt1<<<M_ / 8, 256>>>(x, lnt1_g, lnt1_b);

    // FFN
    hgemm<<<dim3(4, 256), 256, SMEMSZ>>>(p_x1, p_Bffn1, ffn_b1,
                                         p_hid, 512, 512, p_hid, 512, 128, 2);
    hgemm<<<dim3(1, 256), 256, SMEMSZ>>>(p_hid, p_Bffn2, ffn_b2,
                                         p_f2, 128, 128, p_f2, 128, 512, 1);
    k_lnt2<<<M_ / 8, 256>>>(lnt2_g, lnt2_b);

    // fusion
    hgemm<<<dim3(1, 256), 256, SMEMSZ>>>(p_cat, p_Bfus, fus_b,
                                         p_gate, 128, 128, p_gate, 128, 256, 3);
    k_final<<<M_ / 8, 256>>>(x, lnf_g, lnf_b, out);
}